// round 2
// baseline (speedup 1.0000x reference)
#include <cuda_runtime.h>
#include <math.h>
#include <stdint.h>

// ---------------- problem constants ----------------
#define BB   2
#define SS   1024
#define TKN  2048            // BB*SS tokens
#define HID  1024
#define NH   16
#define NKV  4
#define HD   64
#define NEXP 8
#define TOPK 2
#define II   1024

// ---------------- scratch (device globals; no allocs allowed) ----------------
__device__ float g_xn1  [TKN * HID];
__device__ float g_q    [TKN * NH * HD];
__device__ float g_k    [TKN * NKV * HD];
__device__ float g_v    [TKN * NKV * HD];
__device__ float g_ctx  [TKN * HID];
__device__ float g_resid[TKN * HID];
__device__ float g_x2   [TKN * HID];
__device__ float g_gb   [TKN * II];
__device__ float g_ub   [TKN * II];
__device__ float g_hb   [TKN * II];
__device__ float g_sh   [TKN * HID];
__device__ float g_moe  [TKN * HID];
__device__ float g_rprob[TKN * NEXP];
__device__ float g_topv [TKN * TOPK];
__device__ int   g_topi [TKN * TOPK];
__device__ int   g_cnt  [NEXP];
__device__ int   g_idx  [NEXP * TKN];
__device__ float g_wgt  [NEXP * TKN];
__device__ float g_psum [NEXP];
__device__ float g_sgate[TKN];

// ---------------- zero scratch ----------------
__global__ void zero_k(float* moe, int* cnt) {
    int i = blockIdx.x * 256 + threadIdx.x;
    if (i < TKN * HID) moe[i] = 0.f;
    if (i < NEXP) cnt[i] = 0;
}

// ---------------- RMSNorm ----------------
__global__ __launch_bounds__(256) void rmsnorm_k(const float* __restrict__ x,
                                                 const float* __restrict__ w,
                                                 float* __restrict__ y) {
    int t = blockIdx.x;
    __shared__ float red[256];
    const float* xr = x + (size_t)t * HID;
    float s = 0.f;
    for (int i = threadIdx.x; i < HID; i += 256) { float v = xr[i]; s += v * v; }
    red[threadIdx.x] = s; __syncthreads();
    for (int st = 128; st > 0; st >>= 1) {
        if (threadIdx.x < st) red[threadIdx.x] += red[threadIdx.x + st];
        __syncthreads();
    }
    float inv = rsqrtf(red[0] / (float)HID + 1e-6f);
    float* yr = y + (size_t)t * HID;
    for (int i = threadIdx.x; i < HID; i += 256) yr[i] = w[i] * xr[i] * inv;
}

// ---------------- tiled fp32 GEMM: C[M,N] = A[M,K] @ B[K,N] (+addend) ------
// BM=BN=64, BK=16, 256 threads, 4x4 per thread. N,K multiples of 64/16.
#define GBM 64
#define GBN 64
#define GBK 16

__global__ __launch_bounds__(256) void gemm_plain(const float* __restrict__ A,
                                                  const float* __restrict__ B,
                                                  const float* __restrict__ addend,
                                                  float* __restrict__ C,
                                                  int M, int N, int K) {
    __shared__ float As[GBK][GBM + 1];
    __shared__ float Bs[GBK][GBN + 1];
    int row0 = blockIdx.y * GBM, col0 = blockIdx.x * GBN;
    int tid = threadIdx.x, tx = tid & 15, ty = tid >> 4;
    float acc[4][4] = {};
    for (int k0 = 0; k0 < K; k0 += GBK) {
        for (int l = tid; l < GBM * GBK; l += 256) {
            int r = l >> 4, kk = l & 15;
            int gr = row0 + r;
            As[kk][r] = (gr < M) ? A[(size_t)gr * K + k0 + kk] : 0.f;
        }
        for (int l = tid; l < GBK * GBN; l += 256) {
            int c = l & 63, kk = l >> 6;
            Bs[kk][c] = B[(size_t)(k0 + kk) * N + col0 + c];
        }
        __syncthreads();
        #pragma unroll
        for (int kk = 0; kk < GBK; kk++) {
            float a[4], b[4];
            #pragma unroll
            for (int i = 0; i < 4; i++) a[i] = As[kk][ty * 4 + i];
            #pragma unroll
            for (int j = 0; j < 4; j++) b[j] = Bs[kk][tx * 4 + j];
            #pragma unroll
            for (int i = 0; i < 4; i++)
                #pragma unroll
                for (int j = 0; j < 4; j++) acc[i][j] += a[i] * b[j];
        }
        __syncthreads();
    }
    #pragma unroll
    for (int i = 0; i < 4; i++) {
        int r = row0 + ty * 4 + i;
        if (r >= M) continue;
        #pragma unroll
        for (int j = 0; j < 4; j++) {
            int c = col0 + tx * 4 + j;
            float v = acc[i][j];
            if (addend) v += addend[(size_t)r * N + c];
            C[(size_t)r * N + c] = v;
        }
    }
}

// A rows gathered via gidx; M dynamic from cntPtr
__global__ __launch_bounds__(256) void gemm_gather(const float* __restrict__ X,
                                                   const float* __restrict__ B,
                                                   float* __restrict__ C,
                                                   const int* __restrict__ gidx,
                                                   const int* __restrict__ cntPtr,
                                                   int N, int K) {
    int cnt = *cntPtr;
    int row0 = blockIdx.y * GBM, col0 = blockIdx.x * GBN;
    if (row0 >= cnt) return;
    __shared__ float As[GBK][GBM + 1];
    __shared__ float Bs[GBK][GBN + 1];
    int tid = threadIdx.x, tx = tid & 15, ty = tid >> 4;
    float acc[4][4] = {};
    for (int k0 = 0; k0 < K; k0 += GBK) {
        for (int l = tid; l < GBM * GBK; l += 256) {
            int r = l >> 4, kk = l & 15;
            int gr = row0 + r;
            As[kk][r] = (gr < cnt) ? X[(size_t)gidx[gr] * K + k0 + kk] : 0.f;
        }
        for (int l = tid; l < GBK * GBN; l += 256) {
            int c = l & 63, kk = l >> 6;
            Bs[kk][c] = B[(size_t)(k0 + kk) * N + col0 + c];
        }
        __syncthreads();
        #pragma unroll
        for (int kk = 0; kk < GBK; kk++) {
            float a[4], b[4];
            #pragma unroll
            for (int i = 0; i < 4; i++) a[i] = As[kk][ty * 4 + i];
            #pragma unroll
            for (int j = 0; j < 4; j++) b[j] = Bs[kk][tx * 4 + j];
            #pragma unroll
            for (int i = 0; i < 4; i++)
                #pragma unroll
                for (int j = 0; j < 4; j++) acc[i][j] += a[i] * b[j];
        }
        __syncthreads();
    }
    #pragma unroll
    for (int i = 0; i < 4; i++) {
        int r = row0 + ty * 4 + i;
        if (r >= cnt) continue;
        #pragma unroll
        for (int j = 0; j < 4; j++)
            C[(size_t)r * N + col0 + tx * 4 + j] = acc[i][j];
    }
}

// output scattered: out[sidx[r]*N + c] += wgt[r] * acc  (rows unique per launch)
__global__ __launch_bounds__(256) void gemm_scatter(const float* __restrict__ A,
                                                    const float* __restrict__ B,
                                                    float* __restrict__ outAcc,
                                                    const int* __restrict__ sidx,
                                                    const float* __restrict__ wgt,
                                                    const int* __restrict__ cntPtr,
                                                    int N, int K) {
    int cnt = *cntPtr;
    int row0 = blockIdx.y * GBM, col0 = blockIdx.x * GBN;
    if (row0 >= cnt) return;
    __shared__ float As[GBK][GBM + 1];
    __shared__ float Bs[GBK][GBN + 1];
    int tid = threadIdx.x, tx = tid & 15, ty = tid >> 4;
    float acc[4][4] = {};
    for (int k0 = 0; k0 < K; k0 += GBK) {
        for (int l = tid; l < GBM * GBK; l += 256) {
            int r = l >> 4, kk = l & 15;
            int gr = row0 + r;
            As[kk][r] = (gr < cnt) ? A[(size_t)gr * K + k0 + kk] : 0.f;
        }
        for (int l = tid; l < GBK * GBN; l += 256) {
            int c = l & 63, kk = l >> 6;
            Bs[kk][c] = B[(size_t)(k0 + kk) * N + col0 + c];
        }
        __syncthreads();
        #pragma unroll
        for (int kk = 0; kk < GBK; kk++) {
            float a[4], b[4];
            #pragma unroll
            for (int i = 0; i < 4; i++) a[i] = As[kk][ty * 4 + i];
            #pragma unroll
            for (int j = 0; j < 4; j++) b[j] = Bs[kk][tx * 4 + j];
            #pragma unroll
            for (int i = 0; i < 4; i++)
                #pragma unroll
                for (int j = 0; j < 4; j++) acc[i][j] += a[i] * b[j];
        }
        __syncthreads();
    }
    #pragma unroll
    for (int i = 0; i < 4; i++) {
        int r = row0 + ty * 4 + i;
        if (r >= cnt) continue;
        int tok = sidx[r];
        float w = wgt[r];
        #pragma unroll
        for (int j = 0; j < 4; j++) {
            size_t o = (size_t)tok * N + col0 + tx * 4 + j;
            outAcc[o] += w * acc[i][j];
        }
    }
}

// ---------------- RoPE (in-place on q,k) ----------------
__global__ __launch_bounds__(256) void rope_k(float* __restrict__ Q,
                                              float* __restrict__ Kb,
                                              const int* __restrict__ pos_ids) {
    int t = blockIdx.x;
    float pos = (float)pos_ids[t];
    int tid = threadIdx.x;
    // q: NH*32 = 512 rotation pairs
    for (int p = tid; p < NH * 32; p += 256) {
        int hh = p >> 5, d = p & 31;
        float invf = powf(1.0e6f, -(float)d / 32.f);
        float s, c; sincosf(pos * invf, &s, &c);
        size_t base = (size_t)t * (NH * HD) + hh * HD;
        float x1 = Q[base + d], x2 = Q[base + d + 32];
        Q[base + d]      = x1 * c - x2 * s;
        Q[base + d + 32] = x2 * c + x1 * s;
    }
    // k: NKV*32 = 128 rotation pairs
    if (tid < NKV * 32) {
        int hh = tid >> 5, d = tid & 31;
        float invf = powf(1.0e6f, -(float)d / 32.f);
        float s, c; sincosf(pos * invf, &s, &c);
        size_t base = (size_t)t * (NKV * HD) + hh * HD;
        float x1 = Kb[base + d], x2 = Kb[base + d + 32];
        Kb[base + d]      = x1 * c - x2 * s;
        Kb[base + d + 32] = x2 * c + x1 * s;
    }
}

// ---------------- fused causal attention: one block per (b,h,q) -----------
__global__ __launch_bounds__(128) void attn_k(const float* __restrict__ Q,
                                              const float* __restrict__ Kb,
                                              const float* __restrict__ Vb,
                                              float* __restrict__ ctx) {
    int qpos = blockIdx.x, h = blockIdx.y, b = blockIdx.z;
    int kv = h >> 2;                       // NH/NKV = 4 groups
    int t = b * SS + qpos;
    __shared__ float qs[HD];
    __shared__ float probs[SS];
    __shared__ float red[128];
    int tid = threadIdx.x;
    if (tid < HD) qs[tid] = Q[(size_t)t * (NH * HD) + h * HD + tid];
    __syncthreads();
    int nk = qpos + 1;
    float lmax = -1e30f;
    for (int j = tid; j < nk; j += 128) {
        const float* kr = Kb + ((size_t)(b * SS + j)) * (NKV * HD) + kv * HD;
        float s = 0.f;
        #pragma unroll
        for (int d = 0; d < HD; d++) s += qs[d] * kr[d];
        s *= 0.125f;                       // 1/sqrt(64)
        probs[j] = s;
        lmax = fmaxf(lmax, s);
    }
    red[tid] = lmax; __syncthreads();
    for (int st = 64; st > 0; st >>= 1) {
        if (tid < st) red[tid] = fmaxf(red[tid], red[tid + st]);
        __syncthreads();
    }
    float m = red[0]; __syncthreads();
    float lsum = 0.f;
    for (int j = tid; j < nk; j += 128) {
        float e = __expf(probs[j] - m);
        probs[j] = e;
        lsum += e;
    }
    red[tid] = lsum; __syncthreads();
    for (int st = 64; st > 0; st >>= 1) {
        if (tid < st) red[tid] += red[tid + st];
        __syncthreads();
    }
    float inv = 1.f / red[0]; __syncthreads();
    int d = tid & 63, c = tid >> 6;
    float acc = 0.f;
    for (int j = c; j < nk; j += 2)
        acc += probs[j] * Vb[((size_t)(b * SS + j)) * (NKV * HD) + kv * HD + d];
    red[tid] = acc; __syncthreads();
    if (c == 0)
        ctx[(size_t)t * (NH * HD) + h * HD + d] = (red[tid] + red[tid + 64]) * inv;
}

// ---------------- router: logits, softmax, top-2, probs ----------------
__global__ __launch_bounds__(32) void router_k(const float* __restrict__ x2,
                                               const float* __restrict__ rw,
                                               float* __restrict__ rprob,
                                               int* __restrict__ topi,
                                               float* __restrict__ topv) {
    int t = blockIdx.x, lane = threadIdx.x;
    float part[NEXP] = {};
    const float* xr = x2 + (size_t)t * HID;
    for (int k = lane; k < HID; k += 32) {
        float xv = xr[k];
        #pragma unroll
        for (int e = 0; e < NEXP; e++) part[e] += xv * rw[k * NEXP + e];
    }
    #pragma unroll
    for (int e = 0; e < NEXP; e++)
        for (int off = 16; off; off >>= 1)
            part[e] += __shfl_xor_sync(0xffffffff, part[e], off);
    if (lane == 0) {
        float m = part[0];
        #pragma unroll
        for (int e = 1; e < NEXP; e++) m = fmaxf(m, part[e]);
        float p[NEXP], s = 0.f;
        #pragma unroll
        for (int e = 0; e < NEXP; e++) { p[e] = expf(part[e] - m); s += p[e]; }
        #pragma unroll
        for (int e = 0; e < NEXP; e++) { p[e] /= s; rprob[t * NEXP + e] = p[e]; }
        int i1 = 0; float v1 = p[0];
        for (int e = 1; e < NEXP; e++) if (p[e] > v1) { v1 = p[e]; i1 = e; }
        int i2 = -1; float v2 = -1.f;
        for (int e = 0; e < NEXP; e++) if (e != i1 && p[e] > v2) { v2 = p[e]; i2 = e; }
        topi[t * 2]     = i1; topv[t * 2]     = v1;
        topi[t * 2 + 1] = i2; topv[t * 2 + 1] = v2;
    }
}

// deterministic per-expert prob sum (for aux)
__global__ __launch_bounds__(256) void psum_k(const float* __restrict__ rprob,
                                              float* __restrict__ psum) {
    int e = blockIdx.x;
    __shared__ float red[256];
    float s = 0.f;
    for (int t = threadIdx.x; t < TKN; t += 256) s += rprob[t * NEXP + e];
    red[threadIdx.x] = s; __syncthreads();
    for (int st = 128; st > 0; st >>= 1) {
        if (threadIdx.x < st) red[threadIdx.x] += red[threadIdx.x + st];
        __syncthreads();
    }
    if (threadIdx.x == 0) psum[e] = red[0];
}

// build per-expert token lists
__global__ void scatter_k(const int* __restrict__ topi, const float* __restrict__ topv,
                          int* cnt, int* idx, float* wgt) {
    int t = blockIdx.x * 256 + threadIdx.x;
    if (t >= TKN) return;
    for (int j = 0; j < TOPK; j++) {
        int e = topi[t * 2 + j];
        int pos = atomicAdd(&cnt[e], 1);
        idx[e * TKN + pos] = t;
        wgt[e * TKN + pos] = topv[t * 2 + j];
    }
}

// h = silu(g) * u  (M dynamic via cntPtr, nullptr => TKN)
__global__ void silumul_k(const float* __restrict__ g, const float* __restrict__ u,
                          float* __restrict__ h, const int* cntPtr) {
    int M = cntPtr ? *cntPtr : TKN;
    int i = blockIdx.x * 256 + threadIdx.x;
    if (i >= M * II) return;
    float gv = g[i];
    h[i] = (gv / (1.f + __expf(-gv))) * u[i];
}

// shared-expert sigmoid gate
__global__ __launch_bounds__(32) void sgate_k(const float* __restrict__ x2,
                                              const float* __restrict__ seg,
                                              float* __restrict__ sgate) {
    int t = blockIdx.x, lane = threadIdx.x;
    const float* xr = x2 + (size_t)t * HID;
    float s = 0.f;
    for (int k = lane; k < HID; k += 32) s += xr[k] * seg[k];
    for (int off = 16; off; off >>= 1) s += __shfl_xor_sync(0xffffffff, s, off);
    if (lane == 0) sgate[t] = 1.f / (1.f + expf(-s));
}

// out = resid + moe + sgate * shared
__global__ void final_k(const float* __restrict__ resid, const float* __restrict__ moe,
                        const float* __restrict__ sh, const float* __restrict__ sgate,
                        float* __restrict__ out, int n) {
    int i = blockIdx.x * 256 + threadIdx.x;
    if (i >= n) return;
    int t = i >> 10;  // HID = 1024
    out[i] = resid[i] + moe[i] + sgate[t] * sh[i];
}

__global__ void aux_k(const float* __restrict__ psum, float* __restrict__ out,
                      int doWrite, int pos) {
    if (threadIdx.x == 0 && doWrite) {
        float a = 0.f;
        for (int e = 0; e < NEXP; e++) {
            float d = psum[e] / (float)TKN - 1.f / (float)NEXP;
            a += d * d;
        }
        out[pos] = a / (float)NEXP;
    }
}

// ---------------- launch ----------------
extern "C" void kernel_launch(void* const* d_in, const int* in_sizes, int n_in,
                              void* d_out, int out_size) {
    const float* hidden = (const float*)d_in[0];
    /* d_in[1] attention_mask: pure causal, implemented analytically */
    const int*   pos  = (const int*)  d_in[2];
    const float* ln1  = (const float*)d_in[3];
    const float* ln2  = (const float*)d_in[4];
    const float* wq   = (const float*)d_in[5];
    const float* wk   = (const float*)d_in[6];
    const float* wv   = (const float*)d_in[7];
    const float* wo   = (const float*)d_in[8];
    const float* rw   = (const float*)d_in[9];
    const float* egw  = (const float*)d_in[10];
    const float* euw  = (const float*)d_in[11];
    const float* edw  = (const float*)d_in[12];
    const float* sgw  = (const float*)d_in[13];
    const float* suw  = (const float*)d_in[14];
    const float* sdw  = (const float*)d_in[15];
    const float* segw = (const float*)d_in[16];
    float* out = (float*)d_out;

    float *xn1, *q, *k, *v, *ctx, *resid, *x2, *gb, *ub, *hb, *sh, *moe;
    float *rprob, *topv, *wgt, *psum, *sgate;
    int *topi, *cnt, *idx;
    cudaGetSymbolAddress((void**)&xn1,   g_xn1);
    cudaGetSymbolAddress((void**)&q,     g_q);
    cudaGetSymbolAddress((void**)&k,     g_k);
    cudaGetSymbolAddress((void**)&v,     g_v);
    cudaGetSymbolAddress((void**)&ctx,   g_ctx);
    cudaGetSymbolAddress((void**)&resid, g_resid);
    cudaGetSymbolAddress((void**)&x2,    g_x2);
    cudaGetSymbolAddress((void**)&gb,    g_gb);
    cudaGetSymbolAddress((void**)&ub,    g_ub);
    cudaGetSymbolAddress((void**)&hb,    g_hb);
    cudaGetSymbolAddress((void**)&sh,    g_sh);
    cudaGetSymbolAddress((void**)&moe,   g_moe);
    cudaGetSymbolAddress((void**)&rprob, g_rprob);
    cudaGetSymbolAddress((void**)&topv,  g_topv);
    cudaGetSymbolAddress((void**)&topi,  g_topi);
    cudaGetSymbolAddress((void**)&cnt,   g_cnt);
    cudaGetSymbolAddress((void**)&idx,   g_idx);
    cudaGetSymbolAddress((void**)&wgt,   g_wgt);
    cudaGetSymbolAddress((void**)&psum,  g_psum);
    cudaGetSymbolAddress((void**)&sgate, g_sgate);

    zero_k<<<(TKN * HID + 255) / 256, 256>>>(moe, cnt);

    // attention branch
    rmsnorm_k<<<TKN, 256>>>(hidden, ln1, xn1);
    dim3 gFull(HID / GBN, TKN / GBM);           // 16 x 32
    dim3 gKV(256 / GBN, TKN / GBM);             // 4 x 32
    gemm_plain<<<gFull, 256>>>(xn1, wq, nullptr, q, TKN, NH * HD, HID);
    gemm_plain<<<gKV,   256>>>(xn1, wk, nullptr, k, TKN, NKV * HD, HID);
    gemm_plain<<<gKV,   256>>>(xn1, wv, nullptr, v, TKN, NKV * HD, HID);
    rope_k<<<TKN, 256>>>(q, k, pos);
    dim3 gAttn(SS, NH, BB);
    attn_k<<<gAttn, 128>>>(q, k, v, ctx);
    gemm_plain<<<gFull, 256>>>(ctx, wo, hidden, resid, TKN, HID, NH * HD);

    // MoE branch
    rmsnorm_k<<<TKN, 256>>>(resid, ln2, x2);
    router_k<<<TKN, 32>>>(x2, rw, rprob, topi, topv);
    psum_k<<<NEXP, 256>>>(rprob, psum);
    scatter_k<<<(TKN + 255) / 256, 256>>>(topi, topv, cnt, idx, wgt);

    dim3 gExp(II / GBN, TKN / GBM);
    for (int e = 0; e < NEXP; e++) {
        const float* Wg = egw + (size_t)e * HID * II;
        const float* Wu = euw + (size_t)e * HID * II;
        const float* Wd = edw + (size_t)e * II * HID;
        gemm_gather <<<gExp, 256>>>(x2, Wg, gb, idx + e * TKN, cnt + e, II, HID);
        gemm_gather <<<gExp, 256>>>(x2, Wu, ub, idx + e * TKN, cnt + e, II, HID);
        silumul_k   <<<(TKN * II + 255) / 256, 256>>>(gb, ub, hb, cnt + e);
        gemm_scatter<<<gExp, 256>>>(hb, Wd, moe, idx + e * TKN, wgt + e * TKN,
                                    cnt + e, HID, II);
    }

    // shared expert
    gemm_plain<<<gExp, 256>>>(x2, sgw, nullptr, gb, TKN, II, HID);
    gemm_plain<<<gExp, 256>>>(x2, suw, nullptr, ub, TKN, II, HID);
    silumul_k <<<(TKN * II + 255) / 256, 256>>>(gb, ub, hb, nullptr);
    gemm_plain<<<gFull, 256>>>(hb, sdw, nullptr, sh, TKN, HID, II);
    sgate_k<<<TKN, 32>>>(x2, segw, sgate);

    // combine
    int n = TKN * HID;
    int ncopy = out_size < n ? out_size : n;
    final_k<<<(n + 255) / 256, 256>>>(resid, moe, sh, sgate, out, ncopy);
    aux_k<<<1, 32>>>(psum, out, out_size > n ? 1 : 0, n);
}

// round 6
// speedup vs baseline: 2.3534x; 2.3534x over previous
#include <cuda_runtime.h>
#include <math.h>
#include <stdint.h>

// ---------------- problem constants ----------------
#define BB   2
#define SS   1024
#define TKN  2048            // BB*SS tokens
#define HID  1024
#define NH   16
#define NKV  4
#define HD   64
#define NEXP 8
#define TOPK 2
#define II   1024

// ---------------- scratch (device globals; no allocs allowed) ----------------
__device__ float g_xn1  [TKN * HID];
__device__ float g_q    [TKN * NH * HD];
__device__ float g_k    [TKN * NKV * HD];
__device__ float g_v    [TKN * NKV * HD];
__device__ float g_ctx  [TKN * HID];
__device__ float g_resid[TKN * HID];
__device__ float g_x2   [TKN * HID];
__device__ float g_gb   [TKN * II];
__device__ float g_ub   [TKN * II];
__device__ float g_hb   [TKN * II];
__device__ float g_sh   [TKN * HID];
__device__ float g_moe  [TKN * HID];
__device__ float g_rprob[TKN * NEXP];
__device__ float g_topv [TKN * TOPK];
__device__ int   g_topi [TKN * TOPK];
__device__ int   g_cnt  [NEXP];
__device__ int   g_idx  [NEXP * TKN];
__device__ float g_wgt  [NEXP * TKN];
__device__ float g_psum [NEXP];
__device__ float g_sgate[TKN];

// ---------------- zero scratch ----------------
__global__ void zero_k(float* moe, int* cnt) {
    int i = blockIdx.x * 256 + threadIdx.x;
    if (i < TKN * HID) moe[i] = 0.f;
    if (i < NEXP) cnt[i] = 0;
}

// ---------------- RMSNorm ----------------
__global__ __launch_bounds__(256) void rmsnorm_k(const float* __restrict__ x,
                                                 const float* __restrict__ w,
                                                 float* __restrict__ y) {
    int t = blockIdx.x;
    __shared__ float red[256];
    const float* xr = x + (size_t)t * HID;
    float s = 0.f;
    for (int i = threadIdx.x; i < HID; i += 256) { float v = xr[i]; s += v * v; }
    red[threadIdx.x] = s; __syncthreads();
    for (int st = 128; st > 0; st >>= 1) {
        if (threadIdx.x < st) red[threadIdx.x] += red[threadIdx.x + st];
        __syncthreads();
    }
    float inv = rsqrtf(red[0] / (float)HID + 1e-6f);
    float* yr = y + (size_t)t * HID;
    for (int i = threadIdx.x; i < HID; i += 256) yr[i] = w[i] * xr[i] * inv;
}

// ---------------- tf32 helpers ----------------
__device__ __forceinline__ uint32_t f2tf32(float x) {
    uint32_t r;
    asm("cvt.rna.tf32.f32 %0, %1;" : "=r"(r) : "f"(x));
    return r;
}

__device__ __forceinline__ void mma8(float* c, const uint32_t* a, const uint32_t* b) {
    asm volatile(
        "mma.sync.aligned.m16n8k8.row.col.f32.tf32.tf32.f32 "
        "{%0,%1,%2,%3}, {%4,%5,%6,%7}, {%8,%9}, {%0,%1,%2,%3};"
        : "+f"(c[0]), "+f"(c[1]), "+f"(c[2]), "+f"(c[3])
        : "r"(a[0]), "r"(a[1]), "r"(a[2]), "r"(a[3]), "r"(b[0]), "r"(b[1]));
}

// ---------------- tensor-core GEMM (tf32 3x split, ~fp32 accuracy) --------
// C[M,N] = A[M,K] @ B[K,N]; optional row gather (gidx), dynamic M (cntPtr),
// addend (plain mode), or scatter-accumulate (sidx/swgt). N,K % 128/16 == 0.
#define BM 128
#define BN 128
#define BK 16

__global__ __launch_bounds__(256) void gemm_tc(
    const float* __restrict__ A, const float* __restrict__ B,
    float* __restrict__ C, int Mfixed, int N, int K,
    const int* __restrict__ gidx, const int* __restrict__ cntPtr,
    const float* __restrict__ addend,
    const int* __restrict__ sidx, const float* __restrict__ swgt)
{
    int M = cntPtr ? *cntPtr : Mfixed;
    int row0 = blockIdx.y * BM, col0 = blockIdx.x * BN;
    if (row0 >= M) return;
    __shared__ float As[BM][BK + 1];
    __shared__ float Bs[BK][BN + 4];
    int tid = threadIdx.x, wid = tid >> 5, lane = tid & 31;
    int wm = wid >> 2, wn = wid & 3;          // warp tile: 64 rows x 32 cols
    int g = lane >> 2, t4 = lane & 3;
    float acc[4][4][4];
    #pragma unroll
    for (int i = 0; i < 4; i++)
        #pragma unroll
        for (int j = 0; j < 4; j++)
            #pragma unroll
            for (int l = 0; l < 4; l++) acc[i][j][l] = 0.f;

    for (int k0 = 0; k0 < K; k0 += BK) {
        #pragma unroll
        for (int l = 0; l < (BM * BK) / 256; l++) {
            int idx = tid + l * 256;
            int r = idx >> 4, kk = idx & 15;
            int gr = row0 + r;
            float v = 0.f;
            if (gr < M) {
                int ar = gidx ? gidx[gr] : gr;
                v = A[(size_t)ar * K + k0 + kk];
            }
            As[r][kk] = v;
        }
        #pragma unroll
        for (int l = 0; l < (BK * BN) / 256; l++) {
            int idx = tid + l * 256;
            int r = idx >> 7, c = idx & 127;
            Bs[r][c] = B[(size_t)(k0 + r) * N + col0 + c];
        }
        __syncthreads();
        #pragma unroll
        for (int ks = 0; ks < 2; ks++) {
            int kb = ks * 8;
            uint32_t ah[4][4], al[4][4];
            #pragma unroll
            for (int mt = 0; mt < 4; mt++) {
                int r0 = wm * 64 + mt * 16 + g;
                #pragma unroll
                for (int i = 0; i < 4; i++) {
                    int rr = r0 + ((i & 1) ? 8 : 0);
                    int cc = kb + t4 + ((i & 2) ? 4 : 0);
                    float x = As[rr][cc];
                    uint32_t h = f2tf32(x);
                    ah[mt][i] = h;
                    al[mt][i] = f2tf32(x - __uint_as_float(h));
                }
            }
            uint32_t bh[4][2], bl[4][2];
            #pragma unroll
            for (int nt = 0; nt < 4; nt++) {
                int c0 = wn * 32 + nt * 8 + g;
                #pragma unroll
                for (int i = 0; i < 2; i++) {
                    float x = Bs[kb + t4 + i * 4][c0];
                    uint32_t h = f2tf32(x);
                    bh[nt][i] = h;
                    bl[nt][i] = f2tf32(x - __uint_as_float(h));
                }
            }
            #pragma unroll
            for (int mt = 0; mt < 4; mt++)
                #pragma unroll
                for (int nt = 0; nt < 4; nt++) {
                    mma8(acc[mt][nt], ah[mt], bh[nt]);
                    mma8(acc[mt][nt], al[mt], bh[nt]);
                    mma8(acc[mt][nt], ah[mt], bl[nt]);
                }
        }
        __syncthreads();
    }
    // epilogue
    #pragma unroll
    for (int mt = 0; mt < 4; mt++) {
        #pragma unroll
        for (int half = 0; half < 2; half++) {
            int r = row0 + wm * 64 + mt * 16 + g + half * 8;
            if (r >= M) continue;
            int tok = 0; float w = 1.f;
            if (sidx) { tok = sidx[r]; w = swgt[r]; }
            #pragma unroll
            for (int nt = 0; nt < 4; nt++) {
                int c = col0 + wn * 32 + nt * 8 + t4 * 2;
                float v0 = acc[mt][nt][half * 2 + 0];
                float v1 = acc[mt][nt][half * 2 + 1];
                if (sidx) {
                    size_t o = (size_t)tok * N + c;
                    C[o]     += w * v0;
                    C[o + 1] += w * v1;
                } else {
                    size_t o = (size_t)r * N + c;
                    if (addend) { v0 += addend[o]; v1 += addend[o + 1]; }
                    C[o] = v0; C[o + 1] = v1;
                }
            }
        }
    }
}

// ---------------- RoPE (in-place on q,k) ----------------
__global__ __launch_bounds__(256) void rope_k(float* __restrict__ Q,
                                              float* __restrict__ Kb,
                                              const int* __restrict__ pos_ids) {
    int t = blockIdx.x;
    float pos = (float)pos_ids[t];
    int tid = threadIdx.x;
    for (int p = tid; p < NH * 32; p += 256) {
        int hh = p >> 5, d = p & 31;
        float invf = powf(1.0e6f, -(float)d / 32.f);
        float s, c; sincosf(pos * invf, &s, &c);
        size_t base = (size_t)t * (NH * HD) + hh * HD;
        float x1 = Q[base + d], x2 = Q[base + d + 32];
        Q[base + d]      = x1 * c - x2 * s;
        Q[base + d + 32] = x2 * c + x1 * s;
    }
    if (tid < NKV * 32) {
        int hh = tid >> 5, d = tid & 31;
        float invf = powf(1.0e6f, -(float)d / 32.f);
        float s, c; sincosf(pos * invf, &s, &c);
        size_t base = (size_t)t * (NKV * HD) + hh * HD;
        float x1 = Kb[base + d], x2 = Kb[base + d + 32];
        Kb[base + d]      = x1 * c - x2 * s;
        Kb[base + d + 32] = x2 * c + x1 * s;
    }
}

// ---------------- fused causal attention: one block per (b,h,q) -----------
__global__ __launch_bounds__(128) void attn_k(const float* __restrict__ Q,
                                              const float* __restrict__ Kb,
                                              const float* __restrict__ Vb,
                                              float* __restrict__ ctx) {
    int qpos = blockIdx.x, h = blockIdx.y, b = blockIdx.z;
    int kv = h >> 2;                       // NH/NKV = 4 groups
    int t = b * SS + qpos;
    __shared__ float qs[HD];
    __shared__ float probs[SS];
    __shared__ float red[128];
    int tid = threadIdx.x;
    if (tid < HD) qs[tid] = Q[(size_t)t * (NH * HD) + h * HD + tid];
    __syncthreads();
    int nk = qpos + 1;
    float lmax = -1e30f;
    for (int j = tid; j < nk; j += 128) {
        const float4* kr = (const float4*)(Kb + ((size_t)(b * SS + j)) * (NKV * HD) + kv * HD);
        float s = 0.f;
        #pragma unroll
        for (int d = 0; d < 16; d++) {
            float4 k4 = kr[d];
            s += qs[4*d] * k4.x + qs[4*d+1] * k4.y + qs[4*d+2] * k4.z + qs[4*d+3] * k4.w;
        }
        s *= 0.125f;                       // 1/sqrt(64)
        probs[j] = s;
        lmax = fmaxf(lmax, s);
    }
    red[tid] = lmax; __syncthreads();
    for (int st = 64; st > 0; st >>= 1) {
        if (tid < st) red[tid] = fmaxf(red[tid], red[tid + st]);
        __syncthreads();
    }
    float m = red[0]; __syncthreads();
    float lsum = 0.f;
    for (int j = tid; j < nk; j += 128) {
        float e = __expf(probs[j] - m);
        probs[j] = e;
        lsum += e;
    }
    red[tid] = lsum; __syncthreads();
    for (int st = 64; st > 0; st >>= 1) {
        if (tid < st) red[tid] += red[tid + st];
        __syncthreads();
    }
    float inv = 1.f / red[0]; __syncthreads();
    int d = tid & 63, c = tid >> 6;
    float acc = 0.f;
    for (int j = c; j < nk; j += 2)
        acc += probs[j] * Vb[((size_t)(b * SS + j)) * (NKV * HD) + kv * HD + d];
    red[tid] = acc; __syncthreads();
    if (c == 0)
        ctx[(size_t)t * (NH * HD) + h * HD + d] = (red[tid] + red[tid + 64]) * inv;
}

// ---------------- router: logits, softmax, top-2, probs ----------------
__global__ __launch_bounds__(32) void router_k(const float* __restrict__ x2,
                                               const float* __restrict__ rw,
                                               float* __restrict__ rprob,
                                               int* __restrict__ topi,
                                               float* __restrict__ topv) {
    int t = blockIdx.x, lane = threadIdx.x;
    float part[NEXP] = {};
    const float* xr = x2 + (size_t)t * HID;
    for (int k = lane; k < HID; k += 32) {
        float xv = xr[k];
        #pragma unroll
        for (int e = 0; e < NEXP; e++) part[e] += xv * rw[k * NEXP + e];
    }
    #pragma unroll
    for (int e = 0; e < NEXP; e++)
        for (int off = 16; off; off >>= 1)
            part[e] += __shfl_xor_sync(0xffffffff, part[e], off);
    if (lane == 0) {
        float m = part[0];
        #pragma unroll
        for (int e = 1; e < NEXP; e++) m = fmaxf(m, part[e]);
        float p[NEXP], s = 0.f;
        #pragma unroll
        for (int e = 0; e < NEXP; e++) { p[e] = expf(part[e] - m); s += p[e]; }
        #pragma unroll
        for (int e = 0; e < NEXP; e++) { p[e] /= s; rprob[t * NEXP + e] = p[e]; }
        int i1 = 0; float v1 = p[0];
        for (int e = 1; e < NEXP; e++) if (p[e] > v1) { v1 = p[e]; i1 = e; }
        int i2 = -1; float v2 = -1.f;
        for (int e = 0; e < NEXP; e++) if (e != i1 && p[e] > v2) { v2 = p[e]; i2 = e; }
        topi[t * 2]     = i1; topv[t * 2]     = v1;
        topi[t * 2 + 1] = i2; topv[t * 2 + 1] = v2;
    }
}

// deterministic per-expert prob sum (for aux)
__global__ __launch_bounds__(256) void psum_k(const float* __restrict__ rprob,
                                              float* __restrict__ psum) {
    int e = blockIdx.x;
    __shared__ float red[256];
    float s = 0.f;
    for (int t = threadIdx.x; t < TKN; t += 256) s += rprob[t * NEXP + e];
    red[threadIdx.x] = s; __syncthreads();
    for (int st = 128; st > 0; st >>= 1) {
        if (threadIdx.x < st) red[threadIdx.x] += red[threadIdx.x + st];
        __syncthreads();
    }
    if (threadIdx.x == 0) psum[e] = red[0];
}

// build per-expert token lists
__global__ void scatter_k(const int* __restrict__ topi, const float* __restrict__ topv,
                          int* cnt, int* idx, float* wgt) {
    int t = blockIdx.x * 256 + threadIdx.x;
    if (t >= TKN) return;
    for (int j = 0; j < TOPK; j++) {
        int e = topi[t * 2 + j];
        int pos = atomicAdd(&cnt[e], 1);
        idx[e * TKN + pos] = t;
        wgt[e * TKN + pos] = topv[t * 2 + j];
    }
}

// h = silu(g) * u  (M dynamic via cntPtr, nullptr => TKN)
__global__ void silumul_k(const float* __restrict__ g, const float* __restrict__ u,
                          float* __restrict__ h, const int* cntPtr) {
    int M = cntPtr ? *cntPtr : TKN;
    int i = blockIdx.x * 256 + threadIdx.x;
    if (i >= M * II) return;
    float gv = g[i];
    h[i] = (gv / (1.f + __expf(-gv))) * u[i];
}

// shared-expert sigmoid gate
__global__ __launch_bounds__(32) void sgate_k(const float* __restrict__ x2,
                                              const float* __restrict__ seg,
                                              float* __restrict__ sgate) {
    int t = blockIdx.x, lane = threadIdx.x;
    const float* xr = x2 + (size_t)t * HID;
    float s = 0.f;
    for (int k = lane; k < HID; k += 32) s += xr[k] * seg[k];
    for (int off = 16; off; off >>= 1) s += __shfl_xor_sync(0xffffffff, s, off);
    if (lane == 0) sgate[t] = 1.f / (1.f + expf(-s));
}

// out = resid + moe + sgate * shared
__global__ void final_k(const float* __restrict__ resid, const float* __restrict__ moe,
                        const float* __restrict__ sh, const float* __restrict__ sgate,
                        float* __restrict__ out, int n) {
    int i = blockIdx.x * 256 + threadIdx.x;
    if (i >= n) return;
    int t = i >> 10;  // HID = 1024
    out[i] = resid[i] + moe[i] + sgate[t] * sh[i];
}

__global__ void aux_k(const float* __restrict__ psum, float* __restrict__ out,
                      int doWrite, int pos) {
    if (threadIdx.x == 0 && doWrite) {
        float a = 0.f;
        for (int e = 0; e < NEXP; e++) {
            float d = psum[e] / (float)TKN - 1.f / (float)NEXP;
            a += d * d;
        }
        out[pos] = a / (float)NEXP;
    }
}

// ---------------- launch ----------------
extern "C" void kernel_launch(void* const* d_in, const int* in_sizes, int n_in,
                              void* d_out, int out_size) {
    const float* hidden = (const float*)d_in[0];
    /* d_in[1] attention_mask: pure causal, implemented analytically */
    const int*   pos  = (const int*)  d_in[2];
    const float* ln1  = (const float*)d_in[3];
    const float* ln2  = (const float*)d_in[4];
    const float* wq   = (const float*)d_in[5];
    const float* wk   = (const float*)d_in[6];
    const float* wv   = (const float*)d_in[7];
    const float* wo   = (const float*)d_in[8];
    const float* rw   = (const float*)d_in[9];
    const float* egw  = (const float*)d_in[10];
    const float* euw  = (const float*)d_in[11];
    const float* edw  = (const float*)d_in[12];
    const float* sgw  = (const float*)d_in[13];
    const float* suw  = (const float*)d_in[14];
    const float* sdw  = (const float*)d_in[15];
    const float* segw = (const float*)d_in[16];
    float* out = (float*)d_out;

    float *xn1, *q, *k, *v, *ctx, *resid, *x2, *gb, *ub, *hb, *sh, *moe;
    float *rprob, *topv, *wgt, *psum, *sgate;
    int *topi, *cnt, *idx;
    cudaGetSymbolAddress((void**)&xn1,   g_xn1);
    cudaGetSymbolAddress((void**)&q,     g_q);
    cudaGetSymbolAddress((void**)&k,     g_k);
    cudaGetSymbolAddress((void**)&v,     g_v);
    cudaGetSymbolAddress((void**)&ctx,   g_ctx);
    cudaGetSymbolAddress((void**)&resid, g_resid);
    cudaGetSymbolAddress((void**)&x2,    g_x2);
    cudaGetSymbolAddress((void**)&gb,    g_gb);
    cudaGetSymbolAddress((void**)&ub,    g_ub);
    cudaGetSymbolAddress((void**)&hb,    g_hb);
    cudaGetSymbolAddress((void**)&sh,    g_sh);
    cudaGetSymbolAddress((void**)&moe,   g_moe);
    cudaGetSymbolAddress((void**)&rprob, g_rprob);
    cudaGetSymbolAddress((void**)&topv,  g_topv);
    cudaGetSymbolAddress((void**)&topi,  g_topi);
    cudaGetSymbolAddress((void**)&cnt,   g_cnt);
    cudaGetSymbolAddress((void**)&idx,   g_idx);
    cudaGetSymbolAddress((void**)&wgt,   g_wgt);
    cudaGetSymbolAddress((void**)&psum,  g_psum);
    cudaGetSymbolAddress((void**)&sgate, g_sgate);

    zero_k<<<(TKN * HID + 255) / 256, 256>>>(moe, cnt);

    dim3 gFull(HID / BN, TKN / BM);             // 8 x 16
    dim3 gKV((NKV * HD) / BN, TKN / BM);        // 2 x 16
    dim3 gExp(II / BN, TKN / BM);               // 8 x 16

    // attention branch
    rmsnorm_k<<<TKN, 256>>>(hidden, ln1, xn1);
    gemm_tc<<<gFull, 256>>>(xn1, wq, q, TKN, NH * HD, HID, nullptr, nullptr, nullptr, nullptr, nullptr);
    gemm_tc<<<gKV,   256>>>(xn1, wk, k, TKN, NKV * HD, HID, nullptr, nullptr, nullptr, nullptr, nullptr);
    gemm_tc<<<gKV,   256>>>(xn1, wv, v, TKN, NKV * HD, HID, nullptr, nullptr, nullptr, nullptr, nullptr);
    rope_k<<<TKN, 256>>>(q, k, pos);
    dim3 gAttn(SS, NH, BB);
    attn_k<<<gAttn, 128>>>(q, k, v, ctx);
    gemm_tc<<<gFull, 256>>>(ctx, wo, resid, TKN, HID, NH * HD, nullptr, nullptr, hidden, nullptr, nullptr);

    // MoE branch
    rmsnorm_k<<<TKN, 256>>>(resid, ln2, x2);
    router_k<<<TKN, 32>>>(x2, rw, rprob, topi, topv);
    psum_k<<<NEXP, 256>>>(rprob, psum);
    scatter_k<<<(TKN + 255) / 256, 256>>>(topi, topv, cnt, idx, wgt);

    for (int e = 0; e < NEXP; e++) {
        const float* Wg = egw + (size_t)e * HID * II;
        const float* Wu = euw + (size_t)e * HID * II;
        const float* Wd = edw + (size_t)e * II * HID;
        gemm_tc<<<gExp, 256>>>(x2, Wg, gb, TKN, II, HID, idx + e * TKN, cnt + e, nullptr, nullptr, nullptr);
        gemm_tc<<<gExp, 256>>>(x2, Wu, ub, TKN, II, HID, idx + e * TKN, cnt + e, nullptr, nullptr, nullptr);
        silumul_k<<<(TKN * II + 255) / 256, 256>>>(gb, ub, hb, cnt + e);
        gemm_tc<<<gExp, 256>>>(hb, Wd, moe, TKN, HID, II, nullptr, cnt + e, nullptr,
                               idx + e * TKN, wgt + e * TKN);
    }

    // shared expert
    gemm_tc<<<gExp, 256>>>(x2, sgw, gb, TKN, II, HID, nullptr, nullptr, nullptr, nullptr, nullptr);
    gemm_tc<<<gExp, 256>>>(x2, suw, ub, TKN, II, HID, nullptr, nullptr, nullptr, nullptr, nullptr);
    silumul_k<<<(TKN * II + 255) / 256, 256>>>(gb, ub, hb, nullptr);
    gemm_tc<<<gFull, 256>>>(hb, sdw, sh, TKN, HID, II, nullptr, nullptr, nullptr, nullptr, nullptr);
    sgate_k<<<TKN, 32>>>(x2, segw, sgate);

    // combine
    int n = TKN * HID;
    int ncopy = out_size < n ? out_size : n;
    final_k<<<(n + 255) / 256, 256>>>(resid, moe, sh, sgate, out, ncopy);
    aux_k<<<1, 32>>>(psum, out, out_size > n ? 1 : 0, n);
}

// round 7
// speedup vs baseline: 5.0316x; 2.1380x over previous
#include <cuda_runtime.h>
#include <math.h>
#include <stdint.h>

// ---------------- problem constants ----------------
#define BB   2
#define SS   1024
#define TKN  2048            // BB*SS tokens
#define HID  1024
#define NH   16
#define NKV  4
#define HD   64
#define NEXP 8
#define TOPK 2
#define II   1024

// ---------------- scratch (device globals; no allocs allowed) ----------------
__device__ float g_xn1  [TKN * HID];
__device__ float g_q    [TKN * NH * HD];
__device__ float g_k    [TKN * NKV * HD];
__device__ float g_v    [TKN * NKV * HD];
__device__ float g_ctx  [TKN * HID];
__device__ float g_resid[TKN * HID];
__device__ float g_x2   [TKN * HID];
__device__ float g_gb   [TKN * II];
__device__ float g_ub   [TKN * II];
__device__ float g_sh   [TKN * HID];
__device__ float g_e1   [NEXP * TKN * II];   // expert gate / hidden (in-place)
__device__ float g_e2   [NEXP * TKN * II];   // expert up, then down output
__device__ float g_rprob[TKN * NEXP];
__device__ float g_topv [TKN * TOPK];
__device__ int   g_topi [TKN * TOPK];
__device__ int   g_pos  [TKN * TOPK];
__device__ int   g_cnt  [NEXP];
__device__ int   g_idx  [NEXP * TKN];
__device__ float g_psum [NEXP];
__device__ float g_sgate[TKN];

// ---------------- zero counters ----------------
__global__ void zerocnt_k(int* cnt) {
    if (threadIdx.x < NEXP) cnt[threadIdx.x] = 0;
}

// ---------------- RMSNorm ----------------
__global__ __launch_bounds__(256) void rmsnorm_k(const float* __restrict__ x,
                                                 const float* __restrict__ w,
                                                 float* __restrict__ y) {
    int t = blockIdx.x;
    __shared__ float red[256];
    const float* xr = x + (size_t)t * HID;
    float s = 0.f;
    for (int i = threadIdx.x; i < HID; i += 256) { float v = xr[i]; s += v * v; }
    red[threadIdx.x] = s; __syncthreads();
    for (int st = 128; st > 0; st >>= 1) {
        if (threadIdx.x < st) red[threadIdx.x] += red[threadIdx.x + st];
        __syncthreads();
    }
    float inv = rsqrtf(red[0] / (float)HID + 1e-6f);
    float* yr = y + (size_t)t * HID;
    for (int i = threadIdx.x; i < HID; i += 256) yr[i] = w[i] * xr[i] * inv;
}

// ---------------- tf32 helpers ----------------
__device__ __forceinline__ uint32_t f2tf32(float x) {
    uint32_t r;
    asm("cvt.rna.tf32.f32 %0, %1;" : "=r"(r) : "f"(x));
    return r;
}
__device__ __forceinline__ uint2 split2(float x) {
    uint32_t h = f2tf32(x);
    return make_uint2(h, f2tf32(x - __uint_as_float(h)));
}
__device__ __forceinline__ void mma8(float* c, const uint32_t* a, const uint32_t* b) {
    asm volatile(
        "mma.sync.aligned.m16n8k8.row.col.f32.tf32.tf32.f32 "
        "{%0,%1,%2,%3}, {%4,%5,%6,%7}, {%8,%9}, {%0,%1,%2,%3};"
        : "+f"(c[0]), "+f"(c[1]), "+f"(c[2]), "+f"(c[3])
        : "r"(a[0]), "r"(a[1]), "r"(a[2]), "r"(a[3]), "r"(b[0]), "r"(b[1]));
}

// ---------------- tensor-core GEMM (tf32 3x split, smem-resident hi/lo) ----
// C[M,N] = A[M,K] @ B[K,N]; optional row gather (gidx), dynamic per-z M (cntPtr),
// addend. blockIdx.z selects batch slice via Az/Bz/Cz element strides.
#define BM 128
#define BN 128
#define BK 16

__global__ __launch_bounds__(256) void gemm_tc(
    const float* __restrict__ A, const float* __restrict__ B,
    float* __restrict__ C, int Mfixed, int N, int K,
    const int* __restrict__ gidx, const int* __restrict__ cntPtr,
    const float* __restrict__ addend,
    size_t Az, size_t Bz, size_t Cz)
{
    int ez = blockIdx.z;
    int M = cntPtr ? cntPtr[ez] : Mfixed;
    int row0 = blockIdx.y * BM, col0 = blockIdx.x * BN;
    if (row0 >= M) return;
    A += (size_t)ez * Az; B += (size_t)ez * Bz; C += (size_t)ez * Cz;
    if (gidx) gidx += (size_t)ez * TKN;

    __shared__ uint2 As[BM][BK + 1];   // (hi,lo) tf32 pairs
    __shared__ uint2 Bs[BK][BN + 2];

    int tid = threadIdx.x, wid = tid >> 5, lane = tid & 31;
    int wm = wid >> 2, wn = wid & 3;          // warp tile 64x32
    int g = lane >> 2, t4 = lane & 3;

    float acc[4][4][4];
    #pragma unroll
    for (int i = 0; i < 4; i++)
        #pragma unroll
        for (int j = 0; j < 4; j++)
            #pragma unroll
            for (int l = 0; l < 4; l++) acc[i][j][l] = 0.f;

    // per-thread global load coords (2 float4 for A, 2 for B)
    int aRow[2], aCol[2], bRow[2], bCol[2];
    #pragma unroll
    for (int l = 0; l < 2; l++) {
        int f = tid + l * 256;
        aRow[l] = f >> 2;  aCol[l] = (f & 3) * 4;    // 4 float4 per 16-wide row
        bRow[l] = f >> 5;  bCol[l] = (f & 31) * 4;   // 32 float4 per 128-wide row
    }

    float4 aP[2], bP[2];
    // prologue: prefetch chunk 0
    #pragma unroll
    for (int l = 0; l < 2; l++) {
        int gr = row0 + aRow[l];
        if (gr < M) {
            int ar = gidx ? gidx[gr] : gr;
            aP[l] = *(const float4*)&A[(size_t)ar * K + aCol[l]];
        } else aP[l] = make_float4(0.f, 0.f, 0.f, 0.f);
        bP[l] = *(const float4*)&B[(size_t)bRow[l] * N + col0 + bCol[l]];
    }

    int nChunks = K / BK;
    for (int kc = 0; kc < nChunks; kc++) {
        __syncthreads();
        // store prefetched chunk (convert to hi/lo)
        #pragma unroll
        for (int l = 0; l < 2; l++) {
            As[aRow[l]][aCol[l] + 0] = split2(aP[l].x);
            As[aRow[l]][aCol[l] + 1] = split2(aP[l].y);
            As[aRow[l]][aCol[l] + 2] = split2(aP[l].z);
            As[aRow[l]][aCol[l] + 3] = split2(aP[l].w);
            Bs[bRow[l]][bCol[l] + 0] = split2(bP[l].x);
            Bs[bRow[l]][bCol[l] + 1] = split2(bP[l].y);
            Bs[bRow[l]][bCol[l] + 2] = split2(bP[l].z);
            Bs[bRow[l]][bCol[l] + 3] = split2(bP[l].w);
        }
        __syncthreads();
        // prefetch next chunk (hides LDG under compute below)
        if (kc + 1 < nChunks) {
            int k0 = (kc + 1) * BK;
            #pragma unroll
            for (int l = 0; l < 2; l++) {
                int gr = row0 + aRow[l];
                if (gr < M) {
                    int ar = gidx ? gidx[gr] : gr;
                    aP[l] = *(const float4*)&A[(size_t)ar * K + k0 + aCol[l]];
                } else aP[l] = make_float4(0.f, 0.f, 0.f, 0.f);
                bP[l] = *(const float4*)&B[(size_t)(k0 + bRow[l]) * N + col0 + bCol[l]];
            }
        }
        // compute: pure LDS + HMMA
        #pragma unroll
        for (int ks = 0; ks < 2; ks++) {
            int kb = ks * 8;
            uint2 bf[4][2];
            #pragma unroll
            for (int nt = 0; nt < 4; nt++)
                #pragma unroll
                for (int i = 0; i < 2; i++)
                    bf[nt][i] = Bs[kb + t4 + i * 4][wn * 32 + nt * 8 + g];
            #pragma unroll
            for (int mt = 0; mt < 4; mt++) {
                uint2 af[4];
                #pragma unroll
                for (int i = 0; i < 4; i++)
                    af[i] = As[wm * 64 + mt * 16 + g + ((i & 1) ? 8 : 0)]
                              [kb + t4 + ((i & 2) ? 4 : 0)];
                uint32_t ah[4] = {af[0].x, af[1].x, af[2].x, af[3].x};
                uint32_t al[4] = {af[0].y, af[1].y, af[2].y, af[3].y};
                #pragma unroll
                for (int nt = 0; nt < 4; nt++) {
                    uint32_t bh[2] = {bf[nt][0].x, bf[nt][1].x};
                    uint32_t bl[2] = {bf[nt][0].y, bf[nt][1].y};
                    mma8(acc[mt][nt], ah, bh);
                    mma8(acc[mt][nt], al, bh);
                    mma8(acc[mt][nt], ah, bl);
                }
            }
        }
    }
    // epilogue (float2 stores)
    #pragma unroll
    for (int mt = 0; mt < 4; mt++) {
        #pragma unroll
        for (int half = 0; half < 2; half++) {
            int r = row0 + wm * 64 + mt * 16 + g + half * 8;
            if (r >= M) continue;
            #pragma unroll
            for (int nt = 0; nt < 4; nt++) {
                int c = col0 + wn * 32 + nt * 8 + t4 * 2;
                size_t o = (size_t)r * N + c;
                float2 v;
                v.x = acc[mt][nt][half * 2 + 0];
                v.y = acc[mt][nt][half * 2 + 1];
                if (addend) {
                    float2 ad = *(const float2*)&addend[o];
                    v.x += ad.x; v.y += ad.y;
                }
                *(float2*)&C[o] = v;
            }
        }
    }
}

// ---------------- RoPE (in-place on q,k) ----------------
__global__ __launch_bounds__(256) void rope_k(float* __restrict__ Q,
                                              float* __restrict__ Kb,
                                              const int* __restrict__ pos_ids) {
    int t = blockIdx.x;
    float pos = (float)pos_ids[t];
    int tid = threadIdx.x;
    for (int p = tid; p < NH * 32; p += 256) {
        int hh = p >> 5, d = p & 31;
        float invf = powf(1.0e6f, -(float)d / 32.f);
        float s, c; sincosf(pos * invf, &s, &c);
        size_t base = (size_t)t * (NH * HD) + hh * HD;
        float x1 = Q[base + d], x2 = Q[base + d + 32];
        Q[base + d]      = x1 * c - x2 * s;
        Q[base + d + 32] = x2 * c + x1 * s;
    }
    if (tid < NKV * 32) {
        int hh = tid >> 5, d = tid & 31;
        float invf = powf(1.0e6f, -(float)d / 32.f);
        float s, c; sincosf(pos * invf, &s, &c);
        size_t base = (size_t)t * (NKV * HD) + hh * HD;
        float x1 = Kb[base + d], x2 = Kb[base + d + 32];
        Kb[base + d]      = x1 * c - x2 * s;
        Kb[base + d + 32] = x2 * c + x1 * s;
    }
}

// ---------------- fused causal attention: one block per (b,h,q) -----------
__global__ __launch_bounds__(128) void attn_k(const float* __restrict__ Q,
                                              const float* __restrict__ Kb,
                                              const float* __restrict__ Vb,
                                              float* __restrict__ ctx) {
    int qpos = blockIdx.x, h = blockIdx.y, b = blockIdx.z;
    int kv = h >> 2;
    int t = b * SS + qpos;
    __shared__ float qs[HD];
    __shared__ float probs[SS];
    __shared__ float red[128];
    int tid = threadIdx.x;
    if (tid < HD) qs[tid] = Q[(size_t)t * (NH * HD) + h * HD + tid];
    __syncthreads();
    int nk = qpos + 1;
    float lmax = -1e30f;
    for (int j = tid; j < nk; j += 128) {
        const float4* kr = (const float4*)(Kb + ((size_t)(b * SS + j)) * (NKV * HD) + kv * HD);
        float s = 0.f;
        #pragma unroll
        for (int d = 0; d < 16; d++) {
            float4 k4 = kr[d];
            s += qs[4*d] * k4.x + qs[4*d+1] * k4.y + qs[4*d+2] * k4.z + qs[4*d+3] * k4.w;
        }
        s *= 0.125f;
        probs[j] = s;
        lmax = fmaxf(lmax, s);
    }
    red[tid] = lmax; __syncthreads();
    for (int st = 64; st > 0; st >>= 1) {
        if (tid < st) red[tid] = fmaxf(red[tid], red[tid + st]);
        __syncthreads();
    }
    float m = red[0]; __syncthreads();
    float lsum = 0.f;
    for (int j = tid; j < nk; j += 128) {
        float e = __expf(probs[j] - m);
        probs[j] = e;
        lsum += e;
    }
    red[tid] = lsum; __syncthreads();
    for (int st = 64; st > 0; st >>= 1) {
        if (tid < st) red[tid] += red[tid + st];
        __syncthreads();
    }
    float inv = 1.f / red[0]; __syncthreads();
    int d = tid & 63, c = tid >> 6;
    float acc = 0.f;
    for (int j = c; j < nk; j += 2)
        acc += probs[j] * Vb[((size_t)(b * SS + j)) * (NKV * HD) + kv * HD + d];
    red[tid] = acc; __syncthreads();
    if (c == 0)
        ctx[(size_t)t * (NH * HD) + h * HD + d] = (red[tid] + red[tid + 64]) * inv;
}

// ---------------- router ----------------
__global__ __launch_bounds__(32) void router_k(const float* __restrict__ x2,
                                               const float* __restrict__ rw,
                                               float* __restrict__ rprob,
                                               int* __restrict__ topi,
                                               float* __restrict__ topv) {
    int t = blockIdx.x, lane = threadIdx.x;
    float part[NEXP] = {};
    const float* xr = x2 + (size_t)t * HID;
    for (int k = lane; k < HID; k += 32) {
        float xv = xr[k];
        #pragma unroll
        for (int e = 0; e < NEXP; e++) part[e] += xv * rw[k * NEXP + e];
    }
    #pragma unroll
    for (int e = 0; e < NEXP; e++)
        for (int off = 16; off; off >>= 1)
            part[e] += __shfl_xor_sync(0xffffffff, part[e], off);
    if (lane == 0) {
        float m = part[0];
        #pragma unroll
        for (int e = 1; e < NEXP; e++) m = fmaxf(m, part[e]);
        float p[NEXP], s = 0.f;
        #pragma unroll
        for (int e = 0; e < NEXP; e++) { p[e] = expf(part[e] - m); s += p[e]; }
        #pragma unroll
        for (int e = 0; e < NEXP; e++) { p[e] /= s; rprob[t * NEXP + e] = p[e]; }
        int i1 = 0; float v1 = p[0];
        for (int e = 1; e < NEXP; e++) if (p[e] > v1) { v1 = p[e]; i1 = e; }
        int i2 = -1; float v2 = -1.f;
        for (int e = 0; e < NEXP; e++) if (e != i1 && p[e] > v2) { v2 = p[e]; i2 = e; }
        topi[t * 2]     = i1; topv[t * 2]     = v1;
        topi[t * 2 + 1] = i2; topv[t * 2 + 1] = v2;
    }
}

// deterministic per-expert prob sum (for aux)
__global__ __launch_bounds__(256) void psum_k(const float* __restrict__ rprob,
                                              float* __restrict__ psum) {
    int e = blockIdx.x;
    __shared__ float red[256];
    float s = 0.f;
    for (int t = threadIdx.x; t < TKN; t += 256) s += rprob[t * NEXP + e];
    red[threadIdx.x] = s; __syncthreads();
    for (int st = 128; st > 0; st >>= 1) {
        if (threadIdx.x < st) red[threadIdx.x] += red[threadIdx.x + st];
        __syncthreads();
    }
    if (threadIdx.x == 0) psum[e] = red[0];
}

// build per-expert token lists (records position for later gather)
__global__ void scatter_k(const int* __restrict__ topi,
                          int* cnt, int* idx, int* posArr) {
    int t = blockIdx.x * 256 + threadIdx.x;
    if (t >= TKN) return;
    for (int j = 0; j < TOPK; j++) {
        int e = topi[t * 2 + j];
        int pos = atomicAdd(&cnt[e], 1);
        idx[e * TKN + pos] = t;
        posArr[t * 2 + j] = pos;
    }
}

// batched per-expert h = silu(g) * u  (in-place capable)
__global__ void silumulE_k(const float* __restrict__ g, const float* __restrict__ u,
                           float* __restrict__ h, const int* __restrict__ cnt) {
    int e = blockIdx.y;
    int M = cnt[e];
    int i = blockIdx.x * 256 + threadIdx.x;
    if (i >= M * II) return;
    size_t off = (size_t)e * TKN * II + i;
    float gv = g[off];
    h[off] = (gv / (1.f + __expf(-gv))) * u[off];
}

// plain silu-mul over fixed TKN rows (shared expert)
__global__ void silumul_k(const float* __restrict__ g, const float* __restrict__ u,
                          float* __restrict__ h) {
    int i = blockIdx.x * 256 + threadIdx.x;
    if (i >= TKN * II) return;
    float gv = g[i];
    h[i] = (gv / (1.f + __expf(-gv))) * u[i];
}

// shared-expert sigmoid gate
__global__ __launch_bounds__(32) void sgate_k(const float* __restrict__ x2,
                                              const float* __restrict__ seg,
                                              float* __restrict__ sgate) {
    int t = blockIdx.x, lane = threadIdx.x;
    const float* xr = x2 + (size_t)t * HID;
    float s = 0.f;
    for (int k = lane; k < HID; k += 32) s += xr[k] * seg[k];
    for (int off = 16; off; off >>= 1) s += __shfl_xor_sync(0xffffffff, s, off);
    if (lane == 0) sgate[t] = 1.f / (1.f + expf(-s));
}

// out = resid + sum_j topv*expert_down[j] + sgate * shared
__global__ void final_k(const float* __restrict__ resid,
                        const float* __restrict__ yb,     // g_e2 per-expert compact
                        const int* __restrict__ topi, const float* __restrict__ topv,
                        const int* __restrict__ posArr,
                        const float* __restrict__ sh, const float* __restrict__ sgate,
                        float* __restrict__ out, int n) {
    int i = blockIdx.x * 256 + threadIdx.x;
    if (i >= n) return;
    int t = i >> 10;        // HID = 1024
    int col = i & 1023;
    float moe = 0.f;
    #pragma unroll
    for (int j = 0; j < TOPK; j++) {
        int e = topi[t * 2 + j];
        int p = posArr[t * 2 + j];
        moe += topv[t * 2 + j] * yb[((size_t)e * TKN + p) * HID + col];
    }
    out[i] = resid[i] + moe + sgate[t] * sh[i];
}

__global__ void aux_k(const float* __restrict__ psum, float* __restrict__ out,
                      int doWrite, int pos) {
    if (threadIdx.x == 0 && doWrite) {
        float a = 0.f;
        for (int e = 0; e < NEXP; e++) {
            float d = psum[e] / (float)TKN - 1.f / (float)NEXP;
            a += d * d;
        }
        out[pos] = a / (float)NEXP;
    }
}

// ---------------- launch ----------------
extern "C" void kernel_launch(void* const* d_in, const int* in_sizes, int n_in,
                              void* d_out, int out_size) {
    const float* hidden = (const float*)d_in[0];
    const int*   pos  = (const int*)  d_in[2];
    const float* ln1  = (const float*)d_in[3];
    const float* ln2  = (const float*)d_in[4];
    const float* wq   = (const float*)d_in[5];
    const float* wk   = (const float*)d_in[6];
    const float* wv   = (const float*)d_in[7];
    const float* wo   = (const float*)d_in[8];
    const float* rw   = (const float*)d_in[9];
    const float* egw  = (const float*)d_in[10];
    const float* euw  = (const float*)d_in[11];
    const float* edw  = (const float*)d_in[12];
    const float* sgw  = (const float*)d_in[13];
    const float* suw  = (const float*)d_in[14];
    const float* sdw  = (const float*)d_in[15];
    const float* segw = (const float*)d_in[16];
    float* out = (float*)d_out;

    float *xn1, *q, *k, *v, *ctx, *resid, *x2, *gb, *ub, *sh, *e1, *e2;
    float *rprob, *topv, *psum, *sgate;
    int *topi, *cnt, *idx, *posArr;
    cudaGetSymbolAddress((void**)&xn1,   g_xn1);
    cudaGetSymbolAddress((void**)&q,     g_q);
    cudaGetSymbolAddress((void**)&k,     g_k);
    cudaGetSymbolAddress((void**)&v,     g_v);
    cudaGetSymbolAddress((void**)&ctx,   g_ctx);
    cudaGetSymbolAddress((void**)&resid, g_resid);
    cudaGetSymbolAddress((void**)&x2,    g_x2);
    cudaGetSymbolAddress((void**)&gb,    g_gb);
    cudaGetSymbolAddress((void**)&ub,    g_ub);
    cudaGetSymbolAddress((void**)&sh,    g_sh);
    cudaGetSymbolAddress((void**)&e1,    g_e1);
    cudaGetSymbolAddress((void**)&e2,    g_e2);
    cudaGetSymbolAddress((void**)&rprob, g_rprob);
    cudaGetSymbolAddress((void**)&topv,  g_topv);
    cudaGetSymbolAddress((void**)&topi,  g_topi);
    cudaGetSymbolAddress((void**)&posArr,g_pos);
    cudaGetSymbolAddress((void**)&cnt,   g_cnt);
    cudaGetSymbolAddress((void**)&idx,   g_idx);
    cudaGetSymbolAddress((void**)&psum,  g_psum);
    cudaGetSymbolAddress((void**)&sgate, g_sgate);

    zerocnt_k<<<1, 32>>>(cnt);

    dim3 gFull(HID / BN, TKN / BM, 1);          // 8 x 16
    dim3 gKV((NKV * HD) / BN, TKN / BM, 1);     // 2 x 16
    dim3 gExp(II / BN, TKN / BM, NEXP);         // 8 x 16 x 8

    // attention branch
    rmsnorm_k<<<TKN, 256>>>(hidden, ln1, xn1);
    gemm_tc<<<gFull, 256>>>(xn1, wq, q, TKN, NH * HD, HID, nullptr, nullptr, nullptr, 0, 0, 0);
    gemm_tc<<<gKV,   256>>>(xn1, wk, k, TKN, NKV * HD, HID, nullptr, nullptr, nullptr, 0, 0, 0);
    gemm_tc<<<gKV,   256>>>(xn1, wv, v, TKN, NKV * HD, HID, nullptr, nullptr, nullptr, 0, 0, 0);
    rope_k<<<TKN, 256>>>(q, k, pos);
    dim3 gAttn(SS, NH, BB);
    attn_k<<<gAttn, 128>>>(q, k, v, ctx);
    gemm_tc<<<gFull, 256>>>(ctx, wo, resid, TKN, HID, NH * HD, nullptr, nullptr, hidden, 0, 0, 0);

    // MoE branch
    rmsnorm_k<<<TKN, 256>>>(resid, ln2, x2);
    router_k<<<TKN, 32>>>(x2, rw, rprob, topi, topv);
    psum_k<<<NEXP, 256>>>(rprob, psum);
    scatter_k<<<(TKN + 255) / 256, 256>>>(topi, cnt, idx, posArr);

    // batched expert GEMMs (8 experts per launch via grid.z)
    gemm_tc<<<gExp, 256>>>(x2, egw, e1, TKN, II, HID, idx, cnt, nullptr,
                           0, (size_t)HID * II, (size_t)TKN * II);
    gemm_tc<<<gExp, 256>>>(x2, euw, e2, TKN, II, HID, idx, cnt, nullptr,
                           0, (size_t)HID * II, (size_t)TKN * II);
    silumulE_k<<<dim3((TKN * II + 255) / 256, NEXP), 256>>>(e1, e2, e1, cnt);
    gemm_tc<<<gExp, 256>>>(e1, edw, e2, TKN, HID, II, nullptr, cnt, nullptr,
                           (size_t)TKN * II, (size_t)II * HID, (size_t)TKN * HID);

    // shared expert
    gemm_tc<<<gExp.x == 0 ? gFull : dim3(II / BN, TKN / BM, 1), 256>>>(
        x2, sgw, gb, TKN, II, HID, nullptr, nullptr, nullptr, 0, 0, 0);
    gemm_tc<<<dim3(II / BN, TKN / BM, 1), 256>>>(
        x2, suw, ub, TKN, II, HID, nullptr, nullptr, nullptr, 0, 0, 0);
    silumul_k<<<(TKN * II + 255) / 256, 256>>>(gb, ub, gb);
    gemm_tc<<<gFull, 256>>>(gb, sdw, sh, TKN, HID, II, nullptr, nullptr, nullptr, 0, 0, 0);
    sgate_k<<<TKN, 32>>>(x2, segw, sgate);

    // combine
    int n = TKN * HID;
    int ncopy = out_size < n ? out_size : n;
    final_k<<<(n + 255) / 256, 256>>>(resid, e2, topi, topv, posArr, sh, sgate, out, ncopy);
    aux_k<<<1, 32>>>(psum, out, out_size > n ? 1 : 0, n);
}

// round 8
// speedup vs baseline: 14.6066x; 2.9030x over previous
#include <cuda_runtime.h>
#include <math.h>
#include <stdint.h>

// ---------------- problem constants ----------------
#define BB   2
#define SS   1024
#define TKN  2048            // BB*SS tokens
#define HID  1024
#define NH   16
#define NKV  4
#define HD   64
#define NEXP 8
#define TOPK 2
#define II   1024

// ---------------- scratch (device globals; no allocs allowed) ----------------
__device__ float g_xn1  [TKN * HID];
__device__ float g_q    [TKN * NH * HD];
__device__ float g_k    [TKN * NKV * HD];
__device__ float g_v    [TKN * NKV * HD];
__device__ float g_ctx  [TKN * HID];
__device__ float g_resid[TKN * HID];
__device__ float g_x2   [TKN * HID];
__device__ float g_gb   [TKN * II];
__device__ float g_ub   [TKN * II];
__device__ float g_sh   [TKN * HID];
__device__ float g_e1   [NEXP * TKN * II];
__device__ float g_e2   [NEXP * TKN * II];
__device__ float g_rprob[TKN * NEXP];
__device__ float g_topv [TKN * TOPK];
__device__ int   g_topi [TKN * TOPK];
__device__ int   g_pos  [TKN * TOPK];
__device__ int   g_cnt  [NEXP];
__device__ int   g_idx  [NEXP * TKN];
__device__ float g_psum [NEXP];
__device__ float g_sgate[TKN];

// ---------------- zero counters ----------------
__global__ void zerocnt_k(int* cnt) {
    if (threadIdx.x < NEXP) cnt[threadIdx.x] = 0;
}

// ---------------- RMSNorm ----------------
__global__ __launch_bounds__(256) void rmsnorm_k(const float* __restrict__ x,
                                                 const float* __restrict__ w,
                                                 float* __restrict__ y) {
    int t = blockIdx.x;
    __shared__ float red[256];
    const float* xr = x + (size_t)t * HID;
    float s = 0.f;
    for (int i = threadIdx.x; i < HID; i += 256) { float v = xr[i]; s += v * v; }
    red[threadIdx.x] = s; __syncthreads();
    for (int st = 128; st > 0; st >>= 1) {
        if (threadIdx.x < st) red[threadIdx.x] += red[threadIdx.x + st];
        __syncthreads();
    }
    float inv = rsqrtf(red[0] / (float)HID + 1e-6f);
    float* yr = y + (size_t)t * HID;
    for (int i = threadIdx.x; i < HID; i += 256) yr[i] = w[i] * xr[i] * inv;
}

// ---------------- tf32 helpers ----------------
__device__ __forceinline__ uint32_t f2tf32(float x) {
    uint32_t r;
    asm("cvt.rna.tf32.f32 %0, %1;" : "=r"(r) : "f"(x));
    return r;
}
__device__ __forceinline__ void mma8(float* c, const uint32_t* a, const uint32_t* b) {
    asm volatile(
        "mma.sync.aligned.m16n8k8.row.col.f32.tf32.tf32.f32 "
        "{%0,%1,%2,%3}, {%4,%5,%6,%7}, {%8,%9}, {%0,%1,%2,%3};"
        : "+f"(c[0]), "+f"(c[1]), "+f"(c[2]), "+f"(c[3])
        : "r"(a[0]), "r"(a[1]), "r"(a[2]), "r"(a[3]), "r"(b[0]), "r"(b[1]));
}

// ---------------- tensor-core GEMM (plain tf32, smem-resident) ------------
// C[M,N] = A[M,K] @ B[K,N]; optional row gather (gidx), dynamic per-z M,
// addend. blockIdx.z selects batch slice via Az/Bz/Cz element strides.
#define BM 128
#define BN 128
#define BK 16

__global__ __launch_bounds__(256) void gemm_tc(
    const float* __restrict__ A, const float* __restrict__ B,
    float* __restrict__ C, int Mfixed, int N, int K,
    const int* __restrict__ gidx, const int* __restrict__ cntPtr,
    const float* __restrict__ addend,
    size_t Az, size_t Bz, size_t Cz)
{
    int ez = blockIdx.z;
    int M = cntPtr ? cntPtr[ez] : Mfixed;
    int row0 = blockIdx.y * BM, col0 = blockIdx.x * BN;
    if (row0 >= M) return;
    A += (size_t)ez * Az; B += (size_t)ez * Bz; C += (size_t)ez * Cz;
    if (gidx) gidx += (size_t)ez * TKN;

    __shared__ uint32_t As[BM][BK + 1];
    __shared__ uint32_t Bs[BK][BN + 4];

    int tid = threadIdx.x, wid = tid >> 5, lane = tid & 31;
    int wm = wid >> 2, wn = wid & 3;          // warp tile 64x32
    int g = lane >> 2, t4 = lane & 3;

    float acc[4][4][4];
    #pragma unroll
    for (int i = 0; i < 4; i++)
        #pragma unroll
        for (int j = 0; j < 4; j++)
            #pragma unroll
            for (int l = 0; l < 4; l++) acc[i][j][l] = 0.f;

    int aRow[2], aCol[2], bRow[2], bCol[2];
    #pragma unroll
    for (int l = 0; l < 2; l++) {
        int f = tid + l * 256;
        aRow[l] = f >> 2;  aCol[l] = (f & 3) * 4;
        bRow[l] = f >> 5;  bCol[l] = (f & 31) * 4;
    }

    float4 aP[2], bP[2];
    #pragma unroll
    for (int l = 0; l < 2; l++) {
        int gr = row0 + aRow[l];
        if (gr < M) {
            int ar = gidx ? gidx[gr] : gr;
            aP[l] = *(const float4*)&A[(size_t)ar * K + aCol[l]];
        } else aP[l] = make_float4(0.f, 0.f, 0.f, 0.f);
        bP[l] = *(const float4*)&B[(size_t)bRow[l] * N + col0 + bCol[l]];
    }

    int nChunks = K / BK;
    for (int kc = 0; kc < nChunks; kc++) {
        __syncthreads();
        #pragma unroll
        for (int l = 0; l < 2; l++) {
            As[aRow[l]][aCol[l] + 0] = f2tf32(aP[l].x);
            As[aRow[l]][aCol[l] + 1] = f2tf32(aP[l].y);
            As[aRow[l]][aCol[l] + 2] = f2tf32(aP[l].z);
            As[aRow[l]][aCol[l] + 3] = f2tf32(aP[l].w);
            Bs[bRow[l]][bCol[l] + 0] = f2tf32(bP[l].x);
            Bs[bRow[l]][bCol[l] + 1] = f2tf32(bP[l].y);
            Bs[bRow[l]][bCol[l] + 2] = f2tf32(bP[l].z);
            Bs[bRow[l]][bCol[l] + 3] = f2tf32(bP[l].w);
        }
        __syncthreads();
        if (kc + 1 < nChunks) {
            int k0 = (kc + 1) * BK;
            #pragma unroll
            for (int l = 0; l < 2; l++) {
                int gr = row0 + aRow[l];
                if (gr < M) {
                    int ar = gidx ? gidx[gr] : gr;
                    aP[l] = *(const float4*)&A[(size_t)ar * K + k0 + aCol[l]];
                } else aP[l] = make_float4(0.f, 0.f, 0.f, 0.f);
                bP[l] = *(const float4*)&B[(size_t)(k0 + bRow[l]) * N + col0 + bCol[l]];
            }
        }
        #pragma unroll
        for (int ks = 0; ks < 2; ks++) {
            int kb = ks * 8;
            uint32_t bf[4][2];
            #pragma unroll
            for (int nt = 0; nt < 4; nt++)
                #pragma unroll
                for (int i = 0; i < 2; i++)
                    bf[nt][i] = Bs[kb + t4 + i * 4][wn * 32 + nt * 8 + g];
            #pragma unroll
            for (int mt = 0; mt < 4; mt++) {
                uint32_t af[4];
                #pragma unroll
                for (int i = 0; i < 4; i++)
                    af[i] = As[wm * 64 + mt * 16 + g + ((i & 1) ? 8 : 0)]
                              [kb + t4 + ((i & 2) ? 4 : 0)];
                #pragma unroll
                for (int nt = 0; nt < 4; nt++)
                    mma8(acc[mt][nt], af, bf[nt]);
            }
        }
    }
    #pragma unroll
    for (int mt = 0; mt < 4; mt++) {
        #pragma unroll
        for (int half = 0; half < 2; half++) {
            int r = row0 + wm * 64 + mt * 16 + g + half * 8;
            if (r >= M) continue;
            #pragma unroll
            for (int nt = 0; nt < 4; nt++) {
                int c = col0 + wn * 32 + nt * 8 + t4 * 2;
                size_t o = (size_t)r * N + c;
                float2 v;
                v.x = acc[mt][nt][half * 2 + 0];
                v.y = acc[mt][nt][half * 2 + 1];
                if (addend) {
                    float2 ad = *(const float2*)&addend[o];
                    v.x += ad.x; v.y += ad.y;
                }
                *(float2*)&C[o] = v;
            }
        }
    }
}

// ---------------- RoPE (in-place on q,k) ----------------
__global__ __launch_bounds__(256) void rope_k(float* __restrict__ Q,
                                              float* __restrict__ Kb,
                                              const int* __restrict__ pos_ids) {
    int t = blockIdx.x;
    float pos = (float)pos_ids[t];
    int tid = threadIdx.x;
    for (int p = tid; p < NH * 32; p += 256) {
        int hh = p >> 5, d = p & 31;
        float invf = powf(1.0e6f, -(float)d / 32.f);
        float s, c; sincosf(pos * invf, &s, &c);
        size_t base = (size_t)t * (NH * HD) + hh * HD;
        float x1 = Q[base + d], x2 = Q[base + d + 32];
        Q[base + d]      = x1 * c - x2 * s;
        Q[base + d + 32] = x2 * c + x1 * s;
    }
    if (tid < NKV * 32) {
        int hh = tid >> 5, d = tid & 31;
        float invf = powf(1.0e6f, -(float)d / 32.f);
        float s, c; sincosf(pos * invf, &s, &c);
        size_t base = (size_t)t * (NKV * HD) + hh * HD;
        float x1 = Kb[base + d], x2 = Kb[base + d + 32];
        Kb[base + d]      = x1 * c - x2 * s;
        Kb[base + d + 32] = x2 * c + x1 * s;
    }
}

// ---------------- tiled causal attention with online softmax --------------
// block = 256 threads (8 warps), handles TQ=64 queries of one (b,h).
// K/V staged in smem in CKC=32 chunks; each warp owns 8 query rows.
#define TQ  64
#define CKC 32

__global__ __launch_bounds__(256) void attn2_k(const float* __restrict__ Q,
                                               const float* __restrict__ Kb,
                                               const float* __restrict__ Vb,
                                               float* __restrict__ ctx) {
    int qtile = gridDim.x - 1 - blockIdx.x;   // heavy tiles launch first
    int h = blockIdx.y, b = blockIdx.z;
    int kv = h >> 2;
    __shared__ float Qs[TQ][HD];       // 16 KB
    __shared__ float Ks[CKC][68];      // padded for conflict-free col reads
    __shared__ float Vs[CKC][HD];      // 8 KB
    __shared__ float Ps[TQ][CKC];      // 8 KB
    int tid = threadIdx.x, wid = tid >> 5, lane = tid & 31;

    for (int i = tid; i < TQ * HD / 4; i += 256) {
        int r = i >> 4, c4 = i & 15;
        int t = b * SS + qtile * TQ + r;
        ((float4*)Qs[r])[c4] =
            *(const float4*)&Q[(size_t)t * (NH * HD) + h * HD + c4 * 4];
    }

    float m[8], l[8], o0[8], o1[8];
    #pragma unroll
    for (int r = 0; r < 8; r++) { m[r] = -1e30f; l[r] = 0.f; o0[r] = 0.f; o1[r] = 0.f; }
    int row0 = wid * 8;
    int d0 = lane * 2;
    int nch = (qtile + 1) * (TQ / CKC);       // 2*qtile+2

    for (int kc = 0; kc < nch; kc++) {
        __syncthreads();
        for (int i = tid; i < CKC * HD / 4; i += 256) {
            int r = i >> 4, c4 = i & 15;
            int t = b * SS + kc * CKC + r;
            size_t base = (size_t)t * (NKV * HD) + kv * HD + c4 * 4;
            *(float4*)&Ks[r][c4 * 4] = *(const float4*)&Kb[base];
            *(float4*)&Vs[r][c4 * 4] = *(const float4*)&Vb[base];
        }
        __syncthreads();
        // Phase A: scores, column = lane
        float s[8];
        #pragma unroll
        for (int r = 0; r < 8; r++) s[r] = 0.f;
        #pragma unroll 4
        for (int d4 = 0; d4 < 16; d4++) {
            float4 k4 = *(const float4*)&Ks[lane][d4 * 4];
            #pragma unroll
            for (int r = 0; r < 8; r++) {
                float4 q4 = ((const float4*)Qs[row0 + r])[d4];
                s[r] += q4.x * k4.x + q4.y * k4.y + q4.z * k4.z + q4.w * k4.w;
            }
        }
        int kpos = kc * CKC + lane;
        #pragma unroll
        for (int r = 0; r < 8; r++) {
            float sv = s[r] * 0.125f;          // 1/sqrt(64)
            int qpos = qtile * TQ + row0 + r;
            if (kpos > qpos) sv = -1e30f;
            float cm = sv;
            #pragma unroll
            for (int off = 16; off; off >>= 1)
                cm = fmaxf(cm, __shfl_xor_sync(0xffffffffu, cm, off));
            float mnew = fmaxf(m[r], cm);
            float p = __expf(sv - mnew);
            float rs = p;
            #pragma unroll
            for (int off = 16; off; off >>= 1)
                rs += __shfl_xor_sync(0xffffffffu, rs, off);
            float alpha = __expf(m[r] - mnew);
            l[r] = l[r] * alpha + rs;
            o0[r] *= alpha; o1[r] *= alpha;
            m[r] = mnew;
            Ps[row0 + r][lane] = p;
        }
        __syncwarp();
        // Phase B: O += P * V, lane owns dims (d0, d0+1)
        #pragma unroll 4
        for (int kp = 0; kp < CKC / 2; kp++) {
            float2 va = *(const float2*)&Vs[kp * 2][d0];
            float2 vb = *(const float2*)&Vs[kp * 2 + 1][d0];
            #pragma unroll
            for (int r = 0; r < 8; r++) {
                float2 p2 = ((const float2*)Ps[row0 + r])[kp];
                o0[r] += p2.x * va.x + p2.y * vb.x;
                o1[r] += p2.x * va.y + p2.y * vb.y;
            }
        }
    }
    #pragma unroll
    for (int r = 0; r < 8; r++) {
        int t = b * SS + qtile * TQ + row0 + r;
        float inv = 1.f / l[r];
        float2 res = make_float2(o0[r] * inv, o1[r] * inv);
        *(float2*)&ctx[(size_t)t * (NH * HD) + h * HD + d0] = res;
    }
}

// ---------------- router ----------------
__global__ __launch_bounds__(32) void router_k(const float* __restrict__ x2,
                                               const float* __restrict__ rw,
                                               float* __restrict__ rprob,
                                               int* __restrict__ topi,
                                               float* __restrict__ topv) {
    int t = blockIdx.x, lane = threadIdx.x;
    float part[NEXP] = {};
    const float* xr = x2 + (size_t)t * HID;
    for (int k = lane; k < HID; k += 32) {
        float xv = xr[k];
        #pragma unroll
        for (int e = 0; e < NEXP; e++) part[e] += xv * rw[k * NEXP + e];
    }
    #pragma unroll
    for (int e = 0; e < NEXP; e++)
        for (int off = 16; off; off >>= 1)
            part[e] += __shfl_xor_sync(0xffffffff, part[e], off);
    if (lane == 0) {
        float m = part[0];
        #pragma unroll
        for (int e = 1; e < NEXP; e++) m = fmaxf(m, part[e]);
        float p[NEXP], s = 0.f;
        #pragma unroll
        for (int e = 0; e < NEXP; e++) { p[e] = expf(part[e] - m); s += p[e]; }
        #pragma unroll
        for (int e = 0; e < NEXP; e++) { p[e] /= s; rprob[t * NEXP + e] = p[e]; }
        int i1 = 0; float v1 = p[0];
        for (int e = 1; e < NEXP; e++) if (p[e] > v1) { v1 = p[e]; i1 = e; }
        int i2 = -1; float v2 = -1.f;
        for (int e = 0; e < NEXP; e++) if (e != i1 && p[e] > v2) { v2 = p[e]; i2 = e; }
        topi[t * 2]     = i1; topv[t * 2]     = v1;
        topi[t * 2 + 1] = i2; topv[t * 2 + 1] = v2;
    }
}

// deterministic per-expert prob sum (for aux)
__global__ __launch_bounds__(256) void psum_k(const float* __restrict__ rprob,
                                              float* __restrict__ psum) {
    int e = blockIdx.x;
    __shared__ float red[256];
    float s = 0.f;
    for (int t = threadIdx.x; t < TKN; t += 256) s += rprob[t * NEXP + e];
    red[threadIdx.x] = s; __syncthreads();
    for (int st = 128; st > 0; st >>= 1) {
        if (threadIdx.x < st) red[threadIdx.x] += red[threadIdx.x + st];
        __syncthreads();
    }
    if (threadIdx.x == 0) psum[e] = red[0];
}

// build per-expert token lists (records position for later gather)
__global__ void scatter_k(const int* __restrict__ topi,
                          int* cnt, int* idx, int* posArr) {
    int t = blockIdx.x * 256 + threadIdx.x;
    if (t >= TKN) return;
    for (int j = 0; j < TOPK; j++) {
        int e = topi[t * 2 + j];
        int pos = atomicAdd(&cnt[e], 1);
        idx[e * TKN + pos] = t;
        posArr[t * 2 + j] = pos;
    }
}

// batched per-expert h = silu(g) * u  (in-place capable)
__global__ void silumulE_k(const float* __restrict__ g, const float* __restrict__ u,
                           float* __restrict__ h, const int* __restrict__ cnt) {
    int e = blockIdx.y;
    int M = cnt[e];
    int i = blockIdx.x * 256 + threadIdx.x;
    if (i >= M * II) return;
    size_t off = (size_t)e * TKN * II + i;
    float gv = g[off];
    h[off] = (gv / (1.f + __expf(-gv))) * u[off];
}

// plain silu-mul over fixed TKN rows (shared expert)
__global__ void silumul_k(const float* __restrict__ g, const float* __restrict__ u,
                          float* __restrict__ h) {
    int i = blockIdx.x * 256 + threadIdx.x;
    if (i >= TKN * II) return;
    float gv = g[i];
    h[i] = (gv / (1.f + __expf(-gv))) * u[i];
}

// shared-expert sigmoid gate
__global__ __launch_bounds__(32) void sgate_k(const float* __restrict__ x2,
                                              const float* __restrict__ seg,
                                              float* __restrict__ sgate) {
    int t = blockIdx.x, lane = threadIdx.x;
    const float* xr = x2 + (size_t)t * HID;
    float s = 0.f;
    for (int k = lane; k < HID; k += 32) s += xr[k] * seg[k];
    for (int off = 16; off; off >>= 1) s += __shfl_xor_sync(0xffffffff, s, off);
    if (lane == 0) sgate[t] = 1.f / (1.f + expf(-s));
}

// out = resid + sum_j topv*expert_down[j] + sgate * shared
__global__ void final_k(const float* __restrict__ resid,
                        const float* __restrict__ yb,
                        const int* __restrict__ topi, const float* __restrict__ topv,
                        const int* __restrict__ posArr,
                        const float* __restrict__ sh, const float* __restrict__ sgate,
                        float* __restrict__ out, int n) {
    int i = blockIdx.x * 256 + threadIdx.x;
    if (i >= n) return;
    int t = i >> 10;        // HID = 1024
    int col = i & 1023;
    float moe = 0.f;
    #pragma unroll
    for (int j = 0; j < TOPK; j++) {
        int e = topi[t * 2 + j];
        int p = posArr[t * 2 + j];
        moe += topv[t * 2 + j] * yb[((size_t)e * TKN + p) * HID + col];
    }
    out[i] = resid[i] + moe + sgate[t] * sh[i];
}

__global__ void aux_k(const float* __restrict__ psum, float* __restrict__ out,
                      int doWrite, int pos) {
    if (threadIdx.x == 0 && doWrite) {
        float a = 0.f;
        for (int e = 0; e < NEXP; e++) {
            float d = psum[e] / (float)TKN - 1.f / (float)NEXP;
            a += d * d;
        }
        out[pos] = a / (float)NEXP;
    }
}

// ---------------- launch ----------------
extern "C" void kernel_launch(void* const* d_in, const int* in_sizes, int n_in,
                              void* d_out, int out_size) {
    const float* hidden = (const float*)d_in[0];
    const int*   pos  = (const int*)  d_in[2];
    const float* ln1  = (const float*)d_in[3];
    const float* ln2  = (const float*)d_in[4];
    const float* wq   = (const float*)d_in[5];
    const float* wk   = (const float*)d_in[6];
    const float* wv   = (const float*)d_in[7];
    const float* wo   = (const float*)d_in[8];
    const float* rw   = (const float*)d_in[9];
    const float* egw  = (const float*)d_in[10];
    const float* euw  = (const float*)d_in[11];
    const float* edw  = (const float*)d_in[12];
    const float* sgw  = (const float*)d_in[13];
    const float* suw  = (const float*)d_in[14];
    const float* sdw  = (const float*)d_in[15];
    const float* segw = (const float*)d_in[16];
    float* out = (float*)d_out;

    float *xn1, *q, *k, *v, *ctx, *resid, *x2, *gb, *ub, *sh, *e1, *e2;
    float *rprob, *topv, *psum, *sgate;
    int *topi, *cnt, *idx, *posArr;
    cudaGetSymbolAddress((void**)&xn1,   g_xn1);
    cudaGetSymbolAddress((void**)&q,     g_q);
    cudaGetSymbolAddress((void**)&k,     g_k);
    cudaGetSymbolAddress((void**)&v,     g_v);
    cudaGetSymbolAddress((void**)&ctx,   g_ctx);
    cudaGetSymbolAddress((void**)&resid, g_resid);
    cudaGetSymbolAddress((void**)&x2,    g_x2);
    cudaGetSymbolAddress((void**)&gb,    g_gb);
    cudaGetSymbolAddress((void**)&ub,    g_ub);
    cudaGetSymbolAddress((void**)&sh,    g_sh);
    cudaGetSymbolAddress((void**)&e1,    g_e1);
    cudaGetSymbolAddress((void**)&e2,    g_e2);
    cudaGetSymbolAddress((void**)&rprob, g_rprob);
    cudaGetSymbolAddress((void**)&topv,  g_topv);
    cudaGetSymbolAddress((void**)&topi,  g_topi);
    cudaGetSymbolAddress((void**)&posArr,g_pos);
    cudaGetSymbolAddress((void**)&cnt,   g_cnt);
    cudaGetSymbolAddress((void**)&idx,   g_idx);
    cudaGetSymbolAddress((void**)&psum,  g_psum);
    cudaGetSymbolAddress((void**)&sgate, g_sgate);

    zerocnt_k<<<1, 32>>>(cnt);

    dim3 gFull(HID / BN, TKN / BM, 1);          // 8 x 16
    dim3 gKV((NKV * HD) / BN, TKN / BM, 1);     // 2 x 16
    dim3 gII(II / BN, TKN / BM, 1);             // 8 x 16
    dim3 gExp(II / BN, TKN / BM, NEXP);         // 8 x 16 x 8

    // attention branch
    rmsnorm_k<<<TKN, 256>>>(hidden, ln1, xn1);
    gemm_tc<<<gFull, 256>>>(xn1, wq, q, TKN, NH * HD, HID, nullptr, nullptr, nullptr, 0, 0, 0);
    gemm_tc<<<gKV,   256>>>(xn1, wk, k, TKN, NKV * HD, HID, nullptr, nullptr, nullptr, 0, 0, 0);
    gemm_tc<<<gKV,   256>>>(xn1, wv, v, TKN, NKV * HD, HID, nullptr, nullptr, nullptr, 0, 0, 0);
    rope_k<<<TKN, 256>>>(q, k, pos);
    dim3 gAttn(SS / TQ, NH, BB);                // 16 x 16 x 2
    attn2_k<<<gAttn, 256>>>(q, k, v, ctx);
    gemm_tc<<<gFull, 256>>>(ctx, wo, resid, TKN, HID, NH * HD, nullptr, nullptr, hidden, 0, 0, 0);

    // MoE branch
    rmsnorm_k<<<TKN, 256>>>(resid, ln2, x2);
    router_k<<<TKN, 32>>>(x2, rw, rprob, topi, topv);
    psum_k<<<NEXP, 256>>>(rprob, psum);
    scatter_k<<<(TKN + 255) / 256, 256>>>(topi, cnt, idx, posArr);

    // batched expert GEMMs (8 experts per launch via grid.z)
    gemm_tc<<<gExp, 256>>>(x2, egw, e1, TKN, II, HID, idx, cnt, nullptr,
                           0, (size_t)HID * II, (size_t)TKN * II);
    gemm_tc<<<gExp, 256>>>(x2, euw, e2, TKN, II, HID, idx, cnt, nullptr,
                           0, (size_t)HID * II, (size_t)TKN * II);
    silumulE_k<<<dim3((TKN * II + 255) / 256, NEXP), 256>>>(e1, e2, e1, cnt);
    gemm_tc<<<gExp, 256>>>(e1, edw, e2, TKN, HID, II, nullptr, cnt, nullptr,
                           (size_t)TKN * II, (size_t)II * HID, (size_t)TKN * HID);

    // shared expert
    gemm_tc<<<gII, 256>>>(x2, sgw, gb, TKN, II, HID, nullptr, nullptr, nullptr, 0, 0, 0);
    gemm_tc<<<gII, 256>>>(x2, suw, ub, TKN, II, HID, nullptr, nullptr, nullptr, 0, 0, 0);
    silumul_k<<<(TKN * II + 255) / 256, 256>>>(gb, ub, gb);
    gemm_tc<<<gFull, 256>>>(gb, sdw, sh, TKN, HID, II, nullptr, nullptr, nullptr, 0, 0, 0);
    sgate_k<<<TKN, 32>>>(x2, segw, sgate);

    // combine
    int n = TKN * HID;
    int ncopy = out_size < n ? out_size : n;
    final_k<<<(n + 255) / 256, 256>>>(resid, e2, topi, topv, posArr, sh, sgate, out, ncopy);
    aux_k<<<1, 32>>>(psum, out, out_size > n ? 1 : 0, n);
}

// round 11
// speedup vs baseline: 15.4749x; 1.0594x over previous
#include <cuda_runtime.h>
#include <math.h>
#include <stdint.h>

// ---------------- problem constants ----------------
#define BB   2
#define SS   1024
#define TKN  2048            // BB*SS tokens
#define HID  1024
#define NH   16
#define NKV  4
#define HD   64
#define NEXP 8
#define TOPK 2
#define II   1024

// ---------------- scratch (device globals; no allocs allowed) ----------------
__device__ float g_xn1  [TKN * HID];
__device__ float g_q    [TKN * NH * HD];
__device__ float g_k    [TKN * NKV * HD];
__device__ float g_v    [TKN * NKV * HD];
__device__ float g_ctx  [TKN * HID];
__device__ float g_resid[TKN * HID];
__device__ float g_x2   [TKN * HID];
__device__ float g_gb   [TKN * II];
__device__ float g_ub   [TKN * II];
__device__ float g_sh   [TKN * HID];
__device__ float g_e1   [NEXP * TKN * II];   // expert gate
__device__ float g_e2   [NEXP * TKN * II];   // expert up
__device__ float g_eo   [NEXP * TKN * HID];  // expert down output
__device__ float g_rprob[TKN * NEXP];
__device__ float g_topv [TKN * TOPK];
__device__ int   g_topi [TKN * TOPK];
__device__ int   g_pos  [TKN * TOPK];
__device__ int   g_cnt  [NEXP];
__device__ int   g_idx  [NEXP * TKN];
__device__ float g_psum [NEXP];
__device__ float g_sgate[TKN];

// ---------------- zero counters ----------------
__global__ void zerocnt_k(int* cnt) {
    if (threadIdx.x < NEXP) cnt[threadIdx.x] = 0;
}

// ---------------- RMSNorm ----------------
__global__ __launch_bounds__(256) void rmsnorm_k(const float* __restrict__ x,
                                                 const float* __restrict__ w,
                                                 float* __restrict__ y) {
    int t = blockIdx.x;
    __shared__ float red[256];
    const float* xr = x + (size_t)t * HID;
    float s = 0.f;
    for (int i = threadIdx.x; i < HID; i += 256) { float v = xr[i]; s += v * v; }
    red[threadIdx.x] = s; __syncthreads();
    for (int st = 128; st > 0; st >>= 1) {
        if (threadIdx.x < st) red[threadIdx.x] += red[threadIdx.x + st];
        __syncthreads();
    }
    float inv = rsqrtf(red[0] / (float)HID + 1e-6f);
    float* yr = y + (size_t)t * HID;
    for (int i = threadIdx.x; i < HID; i += 256) yr[i] = w[i] * xr[i] * inv;
}

// ---------------- tf32 helpers ----------------
__device__ __forceinline__ uint32_t f2tf32(float x) {
    uint32_t r;
    asm("cvt.rna.tf32.f32 %0, %1;" : "=r"(r) : "f"(x));
    return r;
}
__device__ __forceinline__ void mma8(float* c, const uint32_t* a, const uint32_t* b) {
    asm volatile(
        "mma.sync.aligned.m16n8k8.row.col.f32.tf32.tf32.f32 "
        "{%0,%1,%2,%3}, {%4,%5,%6,%7}, {%8,%9}, {%0,%1,%2,%3};"
        : "+f"(c[0]), "+f"(c[1]), "+f"(c[2]), "+f"(c[3])
        : "r"(a[0]), "r"(a[1]), "r"(a[2]), "r"(a[3]), "r"(b[0]), "r"(b[1]));
}
__device__ __forceinline__ float siluf(float x) {
    return x / (1.f + __expf(-x));
}

// ---------------- tensor-core GEMM (tf32, 2-stage pipelined smem) ---------
// C[M,N] = act(A)[M,K] @ B[K,N]; optional row gather (gidx), per-z dynamic M,
// addend, fused silu-mul (A2: a = silu(a)*a2). z selects slice via strides.
#define BM 128
#define BN 128
#define BK 16

__global__ __launch_bounds__(256) void gemm_tc(
    const float* __restrict__ A, const float* __restrict__ A2,
    const float* __restrict__ B,
    float* __restrict__ C, int Mfixed, int N, int K,
    const int* __restrict__ gidx, const int* __restrict__ cntPtr,
    const float* __restrict__ addend,
    size_t Az, size_t Bz, size_t Cz)
{
    int ez = blockIdx.z;
    int M = cntPtr ? cntPtr[ez] : Mfixed;
    int row0 = blockIdx.y * BM, col0 = blockIdx.x * BN;
    if (row0 >= M) return;
    A += (size_t)ez * Az; B += (size_t)ez * Bz; C += (size_t)ez * Cz;
    if (A2) A2 += (size_t)ez * Az;
    if (gidx) gidx += (size_t)ez * TKN;

    __shared__ uint32_t As[2][BM][BK + 1];
    __shared__ uint32_t Bs[2][BK][BN + 4];

    int tid = threadIdx.x, wid = tid >> 5, lane = tid & 31;
    int wm = wid >> 2, wn = wid & 3;          // warp tile 64x32
    int g = lane >> 2, t4 = lane & 3;

    float acc[4][4][4];
    #pragma unroll
    for (int i = 0; i < 4; i++)
        #pragma unroll
        for (int j = 0; j < 4; j++)
            #pragma unroll
            for (int l = 0; l < 4; l++) acc[i][j][l] = 0.f;

    int aRow[2], aCol[2], bRow[2], bCol[2];
    #pragma unroll
    for (int l = 0; l < 2; l++) {
        int f = tid + l * 256;
        aRow[l] = f >> 2;  aCol[l] = (f & 3) * 4;
        bRow[l] = f >> 5;  bCol[l] = (f & 31) * 4;
    }

    float4 aP[2], bP[2];
    int nChunks = K / BK;

    // LDG of chunk kc into regs
    auto ldg = [&](int kc) {
        int k0 = kc * BK;
        #pragma unroll
        for (int l = 0; l < 2; l++) {
            int gr = row0 + aRow[l];
            if (gr < M) {
                int ar = gidx ? gidx[gr] : gr;
                size_t off = (size_t)ar * K + k0 + aCol[l];
                float4 a = *(const float4*)&A[off];
                if (A2) {
                    float4 u = *(const float4*)&A2[off];
                    a.x = siluf(a.x) * u.x; a.y = siluf(a.y) * u.y;
                    a.z = siluf(a.z) * u.z; a.w = siluf(a.w) * u.w;
                }
                aP[l] = a;
            } else aP[l] = make_float4(0.f, 0.f, 0.f, 0.f);
            bP[l] = *(const float4*)&B[(size_t)(k0 + bRow[l]) * N + col0 + bCol[l]];
        }
    };
    auto sts = [&](int st) {
        #pragma unroll
        for (int l = 0; l < 2; l++) {
            As[st][aRow[l]][aCol[l] + 0] = f2tf32(aP[l].x);
            As[st][aRow[l]][aCol[l] + 1] = f2tf32(aP[l].y);
            As[st][aRow[l]][aCol[l] + 2] = f2tf32(aP[l].z);
            As[st][aRow[l]][aCol[l] + 3] = f2tf32(aP[l].w);
            Bs[st][bRow[l]][bCol[l] + 0] = f2tf32(bP[l].x);
            Bs[st][bRow[l]][bCol[l] + 1] = f2tf32(bP[l].y);
            Bs[st][bRow[l]][bCol[l] + 2] = f2tf32(bP[l].z);
            Bs[st][bRow[l]][bCol[l] + 3] = f2tf32(bP[l].w);
        }
    };

    ldg(0);
    sts(0);
    __syncthreads();
    if (nChunks > 1) ldg(1);

    for (int kc = 0; kc < nChunks; kc++) {
        int cur = kc & 1;
        if (kc + 1 < nChunks) sts(1 - cur);   // store next chunk (regs -> other stage)
        if (kc + 2 < nChunks) ldg(kc + 2);    // prefetch chunk after next
        #pragma unroll
        for (int ks = 0; ks < 2; ks++) {
            int kb = ks * 8;
            uint32_t bf[4][2];
            #pragma unroll
            for (int nt = 0; nt < 4; nt++)
                #pragma unroll
                for (int i = 0; i < 2; i++)
                    bf[nt][i] = Bs[cur][kb + t4 + i * 4][wn * 32 + nt * 8 + g];
            #pragma unroll
            for (int mt = 0; mt < 4; mt++) {
                uint32_t af[4];
                #pragma unroll
                for (int i = 0; i < 4; i++)
                    af[i] = As[cur][wm * 64 + mt * 16 + g + ((i & 1) ? 8 : 0)]
                              [kb + t4 + ((i & 2) ? 4 : 0)];
                #pragma unroll
                for (int nt = 0; nt < 4; nt++)
                    mma8(acc[mt][nt], af, bf[nt]);
            }
        }
        __syncthreads();
    }

    #pragma unroll
    for (int mt = 0; mt < 4; mt++) {
        #pragma unroll
        for (int half = 0; half < 2; half++) {
            int r = row0 + wm * 64 + mt * 16 + g + half * 8;
            if (r >= M) continue;
            #pragma unroll
            for (int nt = 0; nt < 4; nt++) {
                int c = col0 + wn * 32 + nt * 8 + t4 * 2;
                size_t o = (size_t)r * N + c;
                float2 v;
                v.x = acc[mt][nt][half * 2 + 0];
                v.y = acc[mt][nt][half * 2 + 1];
                if (addend) {
                    float2 ad = *(const float2*)&addend[o];
                    v.x += ad.x; v.y += ad.y;
                }
                *(float2*)&C[o] = v;
            }
        }
    }
}

// ---------------- RoPE (in-place on q,k) ----------------
__global__ __launch_bounds__(256) void rope_k(float* __restrict__ Q,
                                              float* __restrict__ Kb,
                                              const int* __restrict__ pos_ids) {
    int t = blockIdx.x;
    float pos = (float)pos_ids[t];
    int tid = threadIdx.x;
    for (int p = tid; p < NH * 32; p += 256) {
        int hh = p >> 5, d = p & 31;
        float invf = powf(1.0e6f, -(float)d / 32.f);
        float s, c; sincosf(pos * invf, &s, &c);
        size_t base = (size_t)t * (NH * HD) + hh * HD;
        float x1 = Q[base + d], x2 = Q[base + d + 32];
        Q[base + d]      = x1 * c - x2 * s;
        Q[base + d + 32] = x2 * c + x1 * s;
    }
    if (tid < NKV * 32) {
        int hh = tid >> 5, d = tid & 31;
        float invf = powf(1.0e6f, -(float)d / 32.f);
        float s, c; sincosf(pos * invf, &s, &c);
        size_t base = (size_t)t * (NKV * HD) + hh * HD;
        float x1 = Kb[base + d], x2 = Kb[base + d + 32];
        Kb[base + d]      = x1 * c - x2 * s;
        Kb[base + d + 32] = x2 * c + x1 * s;
    }
}

// ---------------- tiled causal attention with online softmax --------------
#define TQ  64
#define CKC 32

__global__ __launch_bounds__(256) void attn2_k(const float* __restrict__ Q,
                                               const float* __restrict__ Kb,
                                               const float* __restrict__ Vb,
                                               float* __restrict__ ctx) {
    int qtile = gridDim.x - 1 - blockIdx.x;
    int h = blockIdx.y, b = blockIdx.z;
    int kv = h >> 2;
    __shared__ float Qs[TQ][HD];
    __shared__ float Ks[CKC][68];
    __shared__ float Vs[CKC][HD];
    __shared__ float Ps[TQ][CKC];
    int tid = threadIdx.x, wid = tid >> 5, lane = tid & 31;

    for (int i = tid; i < TQ * HD / 4; i += 256) {
        int r = i >> 4, c4 = i & 15;
        int t = b * SS + qtile * TQ + r;
        ((float4*)Qs[r])[c4] =
            *(const float4*)&Q[(size_t)t * (NH * HD) + h * HD + c4 * 4];
    }

    float m[8], l[8], o0[8], o1[8];
    #pragma unroll
    for (int r = 0; r < 8; r++) { m[r] = -1e30f; l[r] = 0.f; o0[r] = 0.f; o1[r] = 0.f; }
    int row0 = wid * 8;
    int d0 = lane * 2;
    int nch = (qtile + 1) * (TQ / CKC);

    for (int kc = 0; kc < nch; kc++) {
        __syncthreads();
        for (int i = tid; i < CKC * HD / 4; i += 256) {
            int r = i >> 4, c4 = i & 15;
            int t = b * SS + kc * CKC + r;
            size_t base = (size_t)t * (NKV * HD) + kv * HD + c4 * 4;
            *(float4*)&Ks[r][c4 * 4] = *(const float4*)&Kb[base];
            *(float4*)&Vs[r][c4 * 4] = *(const float4*)&Vb[base];
        }
        __syncthreads();
        float s[8];
        #pragma unroll
        for (int r = 0; r < 8; r++) s[r] = 0.f;
        #pragma unroll 4
        for (int d4 = 0; d4 < 16; d4++) {
            float4 k4 = *(const float4*)&Ks[lane][d4 * 4];
            #pragma unroll
            for (int r = 0; r < 8; r++) {
                float4 q4 = ((const float4*)Qs[row0 + r])[d4];
                s[r] += q4.x * k4.x + q4.y * k4.y + q4.z * k4.z + q4.w * k4.w;
            }
        }
        int kpos = kc * CKC + lane;
        #pragma unroll
        for (int r = 0; r < 8; r++) {
            float sv = s[r] * 0.125f;
            int qpos = qtile * TQ + row0 + r;
            if (kpos > qpos) sv = -1e30f;
            float cm = sv;
            #pragma unroll
            for (int off = 16; off; off >>= 1)
                cm = fmaxf(cm, __shfl_xor_sync(0xffffffffu, cm, off));
            float mnew = fmaxf(m[r], cm);
            float p = __expf(sv - mnew);
            float rs = p;
            #pragma unroll
            for (int off = 16; off; off >>= 1)
                rs += __shfl_xor_sync(0xffffffffu, rs, off);
            float alpha = __expf(m[r] - mnew);
            l[r] = l[r] * alpha + rs;
            o0[r] *= alpha; o1[r] *= alpha;
            m[r] = mnew;
            Ps[row0 + r][lane] = p;
        }
        __syncwarp();
        #pragma unroll 4
        for (int kp = 0; kp < CKC / 2; kp++) {
            float2 va = *(const float2*)&Vs[kp * 2][d0];
            float2 vb = *(const float2*)&Vs[kp * 2 + 1][d0];
            #pragma unroll
            for (int r = 0; r < 8; r++) {
                float2 p2 = ((const float2*)Ps[row0 + r])[kp];
                o0[r] += p2.x * va.x + p2.y * vb.x;
                o1[r] += p2.x * va.y + p2.y * vb.y;
            }
        }
    }
    #pragma unroll
    for (int r = 0; r < 8; r++) {
        int t = b * SS + qtile * TQ + row0 + r;
        float inv = 1.f / l[r];
        float2 res = make_float2(o0[r] * inv, o1[r] * inv);
        *(float2*)&ctx[(size_t)t * (NH * HD) + h * HD + d0] = res;
    }
}

// ---------------- router ----------------
__global__ __launch_bounds__(32) void router_k(const float* __restrict__ x2,
                                               const float* __restrict__ rw,
                                               float* __restrict__ rprob,
                                               int* __restrict__ topi,
                                               float* __restrict__ topv) {
    int t = blockIdx.x, lane = threadIdx.x;
    float part[NEXP] = {};
    const float* xr = x2 + (size_t)t * HID;
    for (int k = lane; k < HID; k += 32) {
        float xv = xr[k];
        #pragma unroll
        for (int e = 0; e < NEXP; e++) part[e] += xv * rw[k * NEXP + e];
    }
    #pragma unroll
    for (int e = 0; e < NEXP; e++)
        for (int off = 16; off; off >>= 1)
            part[e] += __shfl_xor_sync(0xffffffff, part[e], off);
    if (lane == 0) {
        float m = part[0];
        #pragma unroll
        for (int e = 1; e < NEXP; e++) m = fmaxf(m, part[e]);
        float p[NEXP], s = 0.f;
        #pragma unroll
        for (int e = 0; e < NEXP; e++) { p[e] = expf(part[e] - m); s += p[e]; }
        #pragma unroll
        for (int e = 0; e < NEXP; e++) { p[e] /= s; rprob[t * NEXP + e] = p[e]; }
        int i1 = 0; float v1 = p[0];
        for (int e = 1; e < NEXP; e++) if (p[e] > v1) { v1 = p[e]; i1 = e; }
        int i2 = -1; float v2 = -1.f;
        for (int e = 0; e < NEXP; e++) if (e != i1 && p[e] > v2) { v2 = p[e]; i2 = e; }
        topi[t * 2]     = i1; topv[t * 2]     = v1;
        topi[t * 2 + 1] = i2; topv[t * 2 + 1] = v2;
    }
}

// deterministic per-expert prob sum (for aux)
__global__ __launch_bounds__(256) void psum_k(const float* __restrict__ rprob,
                                              float* __restrict__ psum) {
    int e = blockIdx.x;
    __shared__ float red[256];
    float s = 0.f;
    for (int t = threadIdx.x; t < TKN; t += 256) s += rprob[t * NEXP + e];
    red[threadIdx.x] = s; __syncthreads();
    for (int st = 128; st > 0; st >>= 1) {
        if (threadIdx.x < st) red[threadIdx.x] += red[threadIdx.x + st];
        __syncthreads();
    }
    if (threadIdx.x == 0) psum[e] = red[0];
}

// build per-expert token lists (records position for later gather)
__global__ void scatter_k(const int* __restrict__ topi,
                          int* cnt, int* idx, int* posArr) {
    int t = blockIdx.x * 256 + threadIdx.x;
    if (t >= TKN) return;
    for (int j = 0; j < TOPK; j++) {
        int e = topi[t * 2 + j];
        int pos = atomicAdd(&cnt[e], 1);
        idx[e * TKN + pos] = t;
        posArr[t * 2 + j] = pos;
    }
}

// shared-expert sigmoid gate
__global__ __launch_bounds__(32) void sgate_k(const float* __restrict__ x2,
                                              const float* __restrict__ seg,
                                              float* __restrict__ sgate) {
    int t = blockIdx.x, lane = threadIdx.x;
    const float* xr = x2 + (size_t)t * HID;
    float s = 0.f;
    for (int k = lane; k < HID; k += 32) s += xr[k] * seg[k];
    for (int off = 16; off; off >>= 1) s += __shfl_xor_sync(0xffffffff, s, off);
    if (lane == 0) sgate[t] = 1.f / (1.f + expf(-s));
}

// out = resid + sum_j topv*expert_down[j] + sgate * shared
__global__ void final_k(const float* __restrict__ resid,
                        const float* __restrict__ yb,
                        const int* __restrict__ topi, const float* __restrict__ topv,
                        const int* __restrict__ posArr,
                        const float* __restrict__ sh, const float* __restrict__ sgate,
                        float* __restrict__ out, int n) {
    int i = blockIdx.x * 256 + threadIdx.x;
    if (i >= n) return;
    int t = i >> 10;
    int col = i & 1023;
    float moe = 0.f;
    #pragma unroll
    for (int j = 0; j < TOPK; j++) {
        int e = topi[t * 2 + j];
        int p = posArr[t * 2 + j];
        moe += topv[t * 2 + j] * yb[((size_t)e * TKN + p) * HID + col];
    }
    out[i] = resid[i] + moe + sgate[t] * sh[i];
}

__global__ void aux_k(const float* __restrict__ psum, float* __restrict__ out,
                      int doWrite, int pos) {
    if (threadIdx.x == 0 && doWrite) {
        float a = 0.f;
        for (int e = 0; e < NEXP; e++) {
            float d = psum[e] / (float)TKN - 1.f / (float)NEXP;
            a += d * d;
        }
        out[pos] = a / (float)NEXP;
    }
}

// ---------------- launch ----------------
extern "C" void kernel_launch(void* const* d_in, const int* in_sizes, int n_in,
                              void* d_out, int out_size) {
    const float* hidden = (const float*)d_in[0];
    const int*   pos  = (const int*)  d_in[2];
    const float* ln1  = (const float*)d_in[3];
    const float* ln2  = (const float*)d_in[4];
    const float* wq   = (const float*)d_in[5];
    const float* wk   = (const float*)d_in[6];
    const float* wv   = (const float*)d_in[7];
    const float* wo   = (const float*)d_in[8];
    const float* rw   = (const float*)d_in[9];
    const float* egw  = (const float*)d_in[10];
    const float* euw  = (const float*)d_in[11];
    const float* edw  = (const float*)d_in[12];
    const float* sgw  = (const float*)d_in[13];
    const float* suw  = (const float*)d_in[14];
    const float* sdw  = (const float*)d_in[15];
    const float* segw = (const float*)d_in[16];
    float* out = (float*)d_out;

    float *xn1, *q, *k, *v, *ctx, *resid, *x2, *gb, *ub, *sh, *e1, *e2, *eo;
    float *rprob, *topv, *psum, *sgate;
    int *topi, *cnt, *idx, *posArr;
    cudaGetSymbolAddress((void**)&xn1,   g_xn1);
    cudaGetSymbolAddress((void**)&q,     g_q);
    cudaGetSymbolAddress((void**)&k,     g_k);
    cudaGetSymbolAddress((void**)&v,     g_v);
    cudaGetSymbolAddress((void**)&ctx,   g_ctx);
    cudaGetSymbolAddress((void**)&resid, g_resid);
    cudaGetSymbolAddress((void**)&x2,    g_x2);
    cudaGetSymbolAddress((void**)&gb,    g_gb);
    cudaGetSymbolAddress((void**)&ub,    g_ub);
    cudaGetSymbolAddress((void**)&sh,    g_sh);
    cudaGetSymbolAddress((void**)&e1,    g_e1);
    cudaGetSymbolAddress((void**)&e2,    g_e2);
    cudaGetSymbolAddress((void**)&eo,    g_eo);
    cudaGetSymbolAddress((void**)&rprob, g_rprob);
    cudaGetSymbolAddress((void**)&topv,  g_topv);
    cudaGetSymbolAddress((void**)&topi,  g_topi);
    cudaGetSymbolAddress((void**)&posArr,g_pos);
    cudaGetSymbolAddress((void**)&cnt,   g_cnt);
    cudaGetSymbolAddress((void**)&idx,   g_idx);
    cudaGetSymbolAddress((void**)&psum,  g_psum);
    cudaGetSymbolAddress((void**)&sgate, g_sgate);

    // streams/events created once, outside graph capture (first call is the
    // correctness run, uncaptured)
    static cudaStream_t s1 = nullptr, s2 = nullptr;
    static cudaEvent_t ev[8];
    if (!s1) {
        cudaStreamCreateWithFlags(&s1, cudaStreamNonBlocking);
        cudaStreamCreateWithFlags(&s2, cudaStreamNonBlocking);
        for (int i = 0; i < 8; i++)
            cudaEventCreateWithFlags(&ev[i], cudaEventDisableTiming);
    }
    cudaStream_t s0 = 0;   // default stream (captured by harness)

    dim3 gFull(HID / BN, TKN / BM, 1);
    dim3 gKV((NKV * HD) / BN, TKN / BM, 1);
    dim3 gII(II / BN, TKN / BM, 1);
    dim3 gExp(II / BN, TKN / BM, NEXP);

    zerocnt_k<<<1, 32, 0, s0>>>(cnt);

    // attention branch
    rmsnorm_k<<<TKN, 256, 0, s0>>>(hidden, ln1, xn1);
    // fork: wk on s1, wv on s2, wq stays on s0
    cudaEventRecord(ev[0], s0);
    cudaStreamWaitEvent(s1, ev[0], 0);
    cudaStreamWaitEvent(s2, ev[0], 0);
    gemm_tc<<<gKV, 256, 0, s1>>>(xn1, nullptr, wk, k, TKN, NKV * HD, HID,
                                 nullptr, nullptr, nullptr, 0, 0, 0);
    gemm_tc<<<gKV, 256, 0, s2>>>(xn1, nullptr, wv, v, TKN, NKV * HD, HID,
                                 nullptr, nullptr, nullptr, 0, 0, 0);
    gemm_tc<<<gFull, 256, 0, s0>>>(xn1, nullptr, wq, q, TKN, NH * HD, HID,
                                   nullptr, nullptr, nullptr, 0, 0, 0);
    cudaEventRecord(ev[1], s1);
    cudaStreamWaitEvent(s0, ev[1], 0);          // join k
    rope_k<<<TKN, 256, 0, s0>>>(q, k, pos);
    cudaEventRecord(ev[2], s2);
    cudaStreamWaitEvent(s0, ev[2], 0);          // join v
    dim3 gAttn(SS / TQ, NH, BB);
    attn2_k<<<gAttn, 256, 0, s0>>>(q, k, v, ctx);
    gemm_tc<<<gFull, 256, 0, s0>>>(ctx, nullptr, wo, resid, TKN, HID, NH * HD,
                                   nullptr, nullptr, hidden, 0, 0, 0);

    // MoE branch
    rmsnorm_k<<<TKN, 256, 0, s0>>>(resid, ln2, x2);

    // fork shared-expert chain onto s1/s2
    cudaEventRecord(ev[3], s0);
    cudaStreamWaitEvent(s1, ev[3], 0);
    cudaStreamWaitEvent(s2, ev[3], 0);
    gemm_tc<<<gII, 256, 0, s1>>>(x2, nullptr, sgw, gb, TKN, II, HID,
                                 nullptr, nullptr, nullptr, 0, 0, 0);
    gemm_tc<<<gII, 256, 0, s2>>>(x2, nullptr, suw, ub, TKN, II, HID,
                                 nullptr, nullptr, nullptr, 0, 0, 0);
    sgate_k<<<TKN, 32, 0, s2>>>(x2, segw, sgate);
    cudaEventRecord(ev[4], s2);
    cudaStreamWaitEvent(s1, ev[4], 0);          // s1: need ub before down-proj
    gemm_tc<<<gFull, 256, 0, s1>>>(gb, ub, sdw, sh, TKN, HID, II,
                                   nullptr, nullptr, nullptr, 0, 0, 0);  // fused silu

    // routed chain on s0
    router_k<<<TKN, 32, 0, s0>>>(x2, rw, rprob, topi, topv);
    psum_k<<<NEXP, 256, 0, s0>>>(rprob, psum);
    scatter_k<<<(TKN + 255) / 256, 256, 0, s0>>>(topi, cnt, idx, posArr);
    gemm_tc<<<gExp, 256, 0, s0>>>(x2, nullptr, egw, e1, TKN, II, HID, idx, cnt,
                                  nullptr, 0, (size_t)HID * II, (size_t)TKN * II);
    gemm_tc<<<gExp, 256, 0, s0>>>(x2, nullptr, euw, e2, TKN, II, HID, idx, cnt,
                                  nullptr, 0, (size_t)HID * II, (size_t)TKN * II);
    gemm_tc<<<gExp, 256, 0, s0>>>(e1, e2, edw, eo, TKN, HID, II, nullptr, cnt,
                                  nullptr, (size_t)TKN * II, (size_t)II * HID,
                                  (size_t)TKN * HID);                    // fused silu

    // join shared chain
    cudaEventRecord(ev[5], s1);
    cudaStreamWaitEvent(s0, ev[5], 0);

    // combine
    int n = TKN * HID;
    int ncopy = out_size < n ? out_size : n;
    final_k<<<(n + 255) / 256, 256, 0, s0>>>(resid, eo, topi, topv, posArr,
                                             sh, sgate, out, ncopy);
    aux_k<<<1, 32, 0, s0>>>(psum, out, out_size > n ? 1 : 0, n);
}

// round 12
// speedup vs baseline: 19.1819x; 1.2396x over previous
#include <cuda_runtime.h>
#include <math.h>
#include <stdint.h>

// ---------------- problem constants ----------------
#define BB   2
#define SS   1024
#define TKN  2048            // BB*SS tokens
#define HID  1024
#define NH   16
#define NKV  4
#define HD   64
#define NEXP 8
#define TOPK 2
#define II   1024

// ---------------- scratch (device globals; no allocs allowed) ----------------
__device__ float g_xn1  [TKN * HID];
__device__ float g_q    [TKN * NH * HD];
__device__ float g_k    [TKN * NKV * HD];
__device__ float g_v    [TKN * NKV * HD];
__device__ float g_ctx  [TKN * HID];
__device__ float g_resid[TKN * HID];
__device__ float g_x2   [TKN * HID];
__device__ float g_gb   [TKN * II];
__device__ float g_ub   [TKN * II];
__device__ float g_sh   [TKN * HID];
__device__ float g_e1   [NEXP * TKN * II];   // expert gate
__device__ float g_e2   [NEXP * TKN * II];   // expert up
__device__ float g_eo   [NEXP * TKN * HID];  // expert down output
__device__ float g_rprob[TKN * NEXP];
__device__ float g_topv [TKN * TOPK];
__device__ int   g_topi [TKN * TOPK];
__device__ int   g_pos  [TKN * TOPK];
__device__ int   g_cnt  [NEXP];
__device__ int   g_idx  [NEXP * TKN];
__device__ float g_psum [NEXP];
__device__ float g_sgate[TKN];

// ---------------- zero counters ----------------
__global__ void zerocnt_k(int* cnt) {
    if (threadIdx.x < NEXP) cnt[threadIdx.x] = 0;
}

// ---------------- RMSNorm ----------------
__global__ __launch_bounds__(256) void rmsnorm_k(const float* __restrict__ x,
                                                 const float* __restrict__ w,
                                                 float* __restrict__ y) {
    int t = blockIdx.x;
    __shared__ float red[256];
    const float* xr = x + (size_t)t * HID;
    float s = 0.f;
    for (int i = threadIdx.x; i < HID; i += 256) { float v = xr[i]; s += v * v; }
    red[threadIdx.x] = s; __syncthreads();
    for (int st = 128; st > 0; st >>= 1) {
        if (threadIdx.x < st) red[threadIdx.x] += red[threadIdx.x + st];
        __syncthreads();
    }
    float inv = rsqrtf(red[0] / (float)HID + 1e-6f);
    float* yr = y + (size_t)t * HID;
    for (int i = threadIdx.x; i < HID; i += 256) yr[i] = w[i] * xr[i] * inv;
}

// ---------------- mma helpers ----------------
__device__ __forceinline__ void mma8(float* c, const uint32_t* a, const uint32_t* b) {
    asm volatile(
        "mma.sync.aligned.m16n8k8.row.col.f32.tf32.tf32.f32 "
        "{%0,%1,%2,%3}, {%4,%5,%6,%7}, {%8,%9}, {%0,%1,%2,%3};"
        : "+f"(c[0]), "+f"(c[1]), "+f"(c[2]), "+f"(c[3])
        : "r"(a[0]), "r"(a[1]), "r"(a[2]), "r"(a[3]), "r"(b[0]), "r"(b[1]));
}
__device__ __forceinline__ float siluf(float x) {
    return x / (1.f + __expf(-x));
}

#define CP_A16(dst, src) \
    asm volatile("cp.async.cg.shared.global [%0], [%1], 16;\n" :: "r"(dst), "l"(src))
#define CP_COMMIT() asm volatile("cp.async.commit_group;\n" ::)
#define CP_WAIT1()  asm volatile("cp.async.wait_group 1;\n" ::)

// ---------------- tensor-core GEMM (tf32 raw-bits, cp.async 3-stage) ------
// C[M,N] = act(A)[M,K] @ B[K,N]; optional row gather (gidx), per-z dynamic M,
// addend, fused silu-mul (A2: a = silu(a)*a2). z selects slice via strides.
// A fragments fed to mma.tf32 as raw fp32 bits (hardware truncates to tf32).
#define BM 128
#define BN 128
#define BK 16
#define STAGES 3
#define ASTR 20     // words; banks (20g + t4) mod 32 all distinct
#define BSTR 136    // words; banks (8*t4 + g) mod 32 all distinct
#define A_ELE (STAGES * BM * ASTR)
#define GSMEM ((STAGES * (BM * ASTR + BK * BSTR)) * 4)

__global__ __launch_bounds__(256, 2) void gemm_tc(
    const float* __restrict__ A, const float* __restrict__ A2,
    const float* __restrict__ B,
    float* __restrict__ C, int Mfixed, int N, int K,
    const int* __restrict__ gidx, const int* __restrict__ cntPtr,
    const float* __restrict__ addend,
    size_t Az, size_t Bz, size_t Cz)
{
    extern __shared__ float sm[];
    int ez = blockIdx.z;
    int M = cntPtr ? cntPtr[ez] : Mfixed;
    int row0 = blockIdx.y * BM, col0 = blockIdx.x * BN;
    if (row0 >= M) return;
    A += (size_t)ez * Az; B += (size_t)ez * Bz; C += (size_t)ez * Cz;
    if (A2) A2 += (size_t)ez * Az;
    if (gidx) gidx += (size_t)ez * TKN;

    int tid = threadIdx.x, wid = tid >> 5, lane = tid & 31;
    int wm = wid >> 2, wn = wid & 3;          // warp tile 64x32
    int g = lane >> 2, t4 = lane & 3;
    uint32_t sbase = (uint32_t)__cvta_generic_to_shared(sm);

    float acc[4][4][4];
    #pragma unroll
    for (int i = 0; i < 4; i++)
        #pragma unroll
        for (int j = 0; j < 4; j++)
            #pragma unroll
            for (int l = 0; l < 4; l++) acc[i][j][l] = 0.f;

    int aRow[2], aCol[2], bRow[2], bCol[2];
    #pragma unroll
    for (int l = 0; l < 2; l++) {
        int f = tid + l * 256;
        aRow[l] = f >> 2;  aCol[l] = (f & 3) * 4;    // 4 float4 per 16-wide row
        bRow[l] = f >> 5;  bCol[l] = (f & 31) * 4;   // 32 float4 per 128-wide row
    }

    int nCh = K / BK;

    auto issue = [&](int kc) {
        if (kc < nCh) {
            int k0 = kc * BK, st = kc % STAGES;
            if (!A2) {
                #pragma unroll
                for (int l = 0; l < 2; l++) {
                    int gr = row0 + aRow[l];
                    if (gr >= M) gr = M - 1;          // clamp: valid addr, row unused
                    int ar = gidx ? gidx[gr] : gr;
                    CP_A16(sbase + (uint32_t)(((st * BM + aRow[l]) * ASTR + aCol[l]) * 4),
                           A + (size_t)ar * K + k0 + aCol[l]);
                }
            } else {
                #pragma unroll
                for (int l = 0; l < 2; l++) {
                    int gr = row0 + aRow[l];
                    int ar = (gr < M) ? gr : (M - 1);
                    size_t off = (size_t)ar * K + k0 + aCol[l];
                    float4 a = *(const float4*)&A[off];
                    float4 u = *(const float4*)&A2[off];
                    a.x = siluf(a.x) * u.x; a.y = siluf(a.y) * u.y;
                    a.z = siluf(a.z) * u.z; a.w = siluf(a.w) * u.w;
                    *(float4*)&sm[(st * BM + aRow[l]) * ASTR + aCol[l]] = a;
                }
            }
            #pragma unroll
            for (int l = 0; l < 2; l++) {
                CP_A16(sbase + (uint32_t)((A_ELE + (st * BK + bRow[l]) * BSTR + bCol[l]) * 4),
                       B + (size_t)(k0 + bRow[l]) * N + col0 + bCol[l]);
            }
        }
        CP_COMMIT();
    };

    issue(0);
    issue(1);

    for (int kc = 0; kc < nCh; kc++) {
        CP_WAIT1();
        __syncthreads();
        issue(kc + 2);
        int cur = kc % STAGES;
        const float* Ab = sm + cur * BM * ASTR;
        const float* Bb = sm + A_ELE + cur * BK * BSTR;
        #pragma unroll
        for (int ks = 0; ks < 2; ks++) {
            int kb = ks * 8;
            uint32_t bf[4][2];
            #pragma unroll
            for (int nt = 0; nt < 4; nt++)
                #pragma unroll
                for (int i = 0; i < 2; i++)
                    bf[nt][i] = __float_as_uint(
                        Bb[(kb + t4 + i * 4) * BSTR + wn * 32 + nt * 8 + g]);
            #pragma unroll
            for (int mt = 0; mt < 4; mt++) {
                uint32_t af[4];
                #pragma unroll
                for (int i = 0; i < 4; i++)
                    af[i] = __float_as_uint(
                        Ab[(wm * 64 + mt * 16 + g + ((i & 1) ? 8 : 0)) * ASTR
                           + kb + t4 + ((i & 2) ? 4 : 0)]);
                #pragma unroll
                for (int nt = 0; nt < 4; nt++)
                    mma8(acc[mt][nt], af, bf[nt]);
            }
        }
    }

    #pragma unroll
    for (int mt = 0; mt < 4; mt++) {
        #pragma unroll
        for (int half = 0; half < 2; half++) {
            int r = row0 + wm * 64 + mt * 16 + g + half * 8;
            if (r >= M) continue;
            #pragma unroll
            for (int nt = 0; nt < 4; nt++) {
                int c = col0 + wn * 32 + nt * 8 + t4 * 2;
                size_t o = (size_t)r * N + c;
                float2 v;
                v.x = acc[mt][nt][half * 2 + 0];
                v.y = acc[mt][nt][half * 2 + 1];
                if (addend) {
                    float2 ad = *(const float2*)&addend[o];
                    v.x += ad.x; v.y += ad.y;
                }
                *(float2*)&C[o] = v;
            }
        }
    }
}

// ---------------- RoPE (in-place on q,k) ----------------
__global__ __launch_bounds__(256) void rope_k(float* __restrict__ Q,
                                              float* __restrict__ Kb,
                                              const int* __restrict__ pos_ids) {
    int t = blockIdx.x;
    float pos = (float)pos_ids[t];
    int tid = threadIdx.x;
    for (int p = tid; p < NH * 32; p += 256) {
        int hh = p >> 5, d = p & 31;
        float invf = powf(1.0e6f, -(float)d / 32.f);
        float s, c; sincosf(pos * invf, &s, &c);
        size_t base = (size_t)t * (NH * HD) + hh * HD;
        float x1 = Q[base + d], x2 = Q[base + d + 32];
        Q[base + d]      = x1 * c - x2 * s;
        Q[base + d + 32] = x2 * c + x1 * s;
    }
    if (tid < NKV * 32) {
        int hh = tid >> 5, d = tid & 31;
        float invf = powf(1.0e6f, -(float)d / 32.f);
        float s, c; sincosf(pos * invf, &s, &c);
        size_t base = (size_t)t * (NKV * HD) + hh * HD;
        float x1 = Kb[base + d], x2 = Kb[base + d + 32];
        Kb[base + d]      = x1 * c - x2 * s;
        Kb[base + d + 32] = x2 * c + x1 * s;
    }
}

// ---------------- tiled causal attention with online softmax --------------
#define TQ  64
#define CKC 32

__global__ __launch_bounds__(256) void attn2_k(const float* __restrict__ Q,
                                               const float* __restrict__ Kb,
                                               const float* __restrict__ Vb,
                                               float* __restrict__ ctx) {
    int qtile = gridDim.x - 1 - blockIdx.x;
    int h = blockIdx.y, b = blockIdx.z;
    int kv = h >> 2;
    __shared__ float Qs[TQ][HD];
    __shared__ float Ks[CKC][68];
    __shared__ float Vs[CKC][HD];
    __shared__ float Ps[TQ][CKC];
    int tid = threadIdx.x, wid = tid >> 5, lane = tid & 31;

    for (int i = tid; i < TQ * HD / 4; i += 256) {
        int r = i >> 4, c4 = i & 15;
        int t = b * SS + qtile * TQ + r;
        ((float4*)Qs[r])[c4] =
            *(const float4*)&Q[(size_t)t * (NH * HD) + h * HD + c4 * 4];
    }

    float m[8], l[8], o0[8], o1[8];
    #pragma unroll
    for (int r = 0; r < 8; r++) { m[r] = -1e30f; l[r] = 0.f; o0[r] = 0.f; o1[r] = 0.f; }
    int row0 = wid * 8;
    int d0 = lane * 2;
    int nch = (qtile + 1) * (TQ / CKC);

    for (int kc = 0; kc < nch; kc++) {
        __syncthreads();
        for (int i = tid; i < CKC * HD / 4; i += 256) {
            int r = i >> 4, c4 = i & 15;
            int t = b * SS + kc * CKC + r;
            size_t base = (size_t)t * (NKV * HD) + kv * HD + c4 * 4;
            *(float4*)&Ks[r][c4 * 4] = *(const float4*)&Kb[base];
            *(float4*)&Vs[r][c4 * 4] = *(const float4*)&Vb[base];
        }
        __syncthreads();
        float s[8];
        #pragma unroll
        for (int r = 0; r < 8; r++) s[r] = 0.f;
        #pragma unroll 4
        for (int d4 = 0; d4 < 16; d4++) {
            float4 k4 = *(const float4*)&Ks[lane][d4 * 4];
            #pragma unroll
            for (int r = 0; r < 8; r++) {
                float4 q4 = ((const float4*)Qs[row0 + r])[d4];
                s[r] += q4.x * k4.x + q4.y * k4.y + q4.z * k4.z + q4.w * k4.w;
            }
        }
        int kpos = kc * CKC + lane;
        #pragma unroll
        for (int r = 0; r < 8; r++) {
            float sv = s[r] * 0.125f;
            int qpos = qtile * TQ + row0 + r;
            if (kpos > qpos) sv = -1e30f;
            float cm = sv;
            #pragma unroll
            for (int off = 16; off; off >>= 1)
                cm = fmaxf(cm, __shfl_xor_sync(0xffffffffu, cm, off));
            float mnew = fmaxf(m[r], cm);
            float p = __expf(sv - mnew);
            float rs = p;
            #pragma unroll
            for (int off = 16; off; off >>= 1)
                rs += __shfl_xor_sync(0xffffffffu, rs, off);
            float alpha = __expf(m[r] - mnew);
            l[r] = l[r] * alpha + rs;
            o0[r] *= alpha; o1[r] *= alpha;
            m[r] = mnew;
            Ps[row0 + r][lane] = p;
        }
        __syncwarp();
        #pragma unroll 4
        for (int kp = 0; kp < CKC / 2; kp++) {
            float2 va = *(const float2*)&Vs[kp * 2][d0];
            float2 vb = *(const float2*)&Vs[kp * 2 + 1][d0];
            #pragma unroll
            for (int r = 0; r < 8; r++) {
                float2 p2 = ((const float2*)Ps[row0 + r])[kp];
                o0[r] += p2.x * va.x + p2.y * vb.x;
                o1[r] += p2.x * va.y + p2.y * vb.y;
            }
        }
    }
    #pragma unroll
    for (int r = 0; r < 8; r++) {
        int t = b * SS + qtile * TQ + row0 + r;
        float inv = 1.f / l[r];
        float2 res = make_float2(o0[r] * inv, o1[r] * inv);
        *(float2*)&ctx[(size_t)t * (NH * HD) + h * HD + d0] = res;
    }
}

// ---------------- router ----------------
__global__ __launch_bounds__(32) void router_k(const float* __restrict__ x2,
                                               const float* __restrict__ rw,
                                               float* __restrict__ rprob,
                                               int* __restrict__ topi,
                                               float* __restrict__ topv) {
    int t = blockIdx.x, lane = threadIdx.x;
    float part[NEXP] = {};
    const float* xr = x2 + (size_t)t * HID;
    for (int k = lane; k < HID; k += 32) {
        float xv = xr[k];
        #pragma unroll
        for (int e = 0; e < NEXP; e++) part[e] += xv * rw[k * NEXP + e];
    }
    #pragma unroll
    for (int e = 0; e < NEXP; e++)
        for (int off = 16; off; off >>= 1)
            part[e] += __shfl_xor_sync(0xffffffff, part[e], off);
    if (lane == 0) {
        float m = part[0];
        #pragma unroll
        for (int e = 1; e < NEXP; e++) m = fmaxf(m, part[e]);
        float p[NEXP], s = 0.f;
        #pragma unroll
        for (int e = 0; e < NEXP; e++) { p[e] = expf(part[e] - m); s += p[e]; }
        #pragma unroll
        for (int e = 0; e < NEXP; e++) { p[e] /= s; rprob[t * NEXP + e] = p[e]; }
        int i1 = 0; float v1 = p[0];
        for (int e = 1; e < NEXP; e++) if (p[e] > v1) { v1 = p[e]; i1 = e; }
        int i2 = -1; float v2 = -1.f;
        for (int e = 0; e < NEXP; e++) if (e != i1 && p[e] > v2) { v2 = p[e]; i2 = e; }
        topi[t * 2]     = i1; topv[t * 2]     = v1;
        topi[t * 2 + 1] = i2; topv[t * 2 + 1] = v2;
    }
}

// deterministic per-expert prob sum (for aux)
__global__ __launch_bounds__(256) void psum_k(const float* __restrict__ rprob,
                                              float* __restrict__ psum) {
    int e = blockIdx.x;
    __shared__ float red[256];
    float s = 0.f;
    for (int t = threadIdx.x; t < TKN; t += 256) s += rprob[t * NEXP + e];
    red[threadIdx.x] = s; __syncthreads();
    for (int st = 128; st > 0; st >>= 1) {
        if (threadIdx.x < st) red[threadIdx.x] += red[threadIdx.x + st];
        __syncthreads();
    }
    if (threadIdx.x == 0) psum[e] = red[0];
}

// build per-expert token lists (records position for later gather)
__global__ void scatter_k(const int* __restrict__ topi,
                          int* cnt, int* idx, int* posArr) {
    int t = blockIdx.x * 256 + threadIdx.x;
    if (t >= TKN) return;
    for (int j = 0; j < TOPK; j++) {
        int e = topi[t * 2 + j];
        int pos = atomicAdd(&cnt[e], 1);
        idx[e * TKN + pos] = t;
        posArr[t * 2 + j] = pos;
    }
}

// shared-expert sigmoid gate
__global__ __launch_bounds__(32) void sgate_k(const float* __restrict__ x2,
                                              const float* __restrict__ seg,
                                              float* __restrict__ sgate) {
    int t = blockIdx.x, lane = threadIdx.x;
    const float* xr = x2 + (size_t)t * HID;
    float s = 0.f;
    for (int k = lane; k < HID; k += 32) s += xr[k] * seg[k];
    for (int off = 16; off; off >>= 1) s += __shfl_xor_sync(0xffffffff, s, off);
    if (lane == 0) sgate[t] = 1.f / (1.f + expf(-s));
}

// out = resid + sum_j topv*expert_down[j] + sgate * shared
__global__ void final_k(const float* __restrict__ resid,
                        const float* __restrict__ yb,
                        const int* __restrict__ topi, const float* __restrict__ topv,
                        const int* __restrict__ posArr,
                        const float* __restrict__ sh, const float* __restrict__ sgate,
                        float* __restrict__ out, int n) {
    int i = blockIdx.x * 256 + threadIdx.x;
    if (i >= n) return;
    int t = i >> 10;
    int col = i & 1023;
    float moe = 0.f;
    #pragma unroll
    for (int j = 0; j < TOPK; j++) {
        int e = topi[t * 2 + j];
        int p = posArr[t * 2 + j];
        moe += topv[t * 2 + j] * yb[((size_t)e * TKN + p) * HID + col];
    }
    out[i] = resid[i] + moe + sgate[t] * sh[i];
}

__global__ void aux_k(const float* __restrict__ psum, float* __restrict__ out,
                      int doWrite, int pos) {
    if (threadIdx.x == 0 && doWrite) {
        float a = 0.f;
        for (int e = 0; e < NEXP; e++) {
            float d = psum[e] / (float)TKN - 1.f / (float)NEXP;
            a += d * d;
        }
        out[pos] = a / (float)NEXP;
    }
}

// ---------------- launch ----------------
extern "C" void kernel_launch(void* const* d_in, const int* in_sizes, int n_in,
                              void* d_out, int out_size) {
    const float* hidden = (const float*)d_in[0];
    const int*   pos  = (const int*)  d_in[2];
    const float* ln1  = (const float*)d_in[3];
    const float* ln2  = (const float*)d_in[4];
    const float* wq   = (const float*)d_in[5];
    const float* wk   = (const float*)d_in[6];
    const float* wv   = (const float*)d_in[7];
    const float* wo   = (const float*)d_in[8];
    const float* rw   = (const float*)d_in[9];
    const float* egw  = (const float*)d_in[10];
    const float* euw  = (const float*)d_in[11];
    const float* edw  = (const float*)d_in[12];
    const float* sgw  = (const float*)d_in[13];
    const float* suw  = (const float*)d_in[14];
    const float* sdw  = (const float*)d_in[15];
    const float* segw = (const float*)d_in[16];
    float* out = (float*)d_out;

    float *xn1, *q, *k, *v, *ctx, *resid, *x2, *gb, *ub, *sh, *e1, *e2, *eo;
    float *rprob, *topv, *psum, *sgate;
    int *topi, *cnt, *idx, *posArr;
    cudaGetSymbolAddress((void**)&xn1,   g_xn1);
    cudaGetSymbolAddress((void**)&q,     g_q);
    cudaGetSymbolAddress((void**)&k,     g_k);
    cudaGetSymbolAddress((void**)&v,     g_v);
    cudaGetSymbolAddress((void**)&ctx,   g_ctx);
    cudaGetSymbolAddress((void**)&resid, g_resid);
    cudaGetSymbolAddress((void**)&x2,    g_x2);
    cudaGetSymbolAddress((void**)&gb,    g_gb);
    cudaGetSymbolAddress((void**)&ub,    g_ub);
    cudaGetSymbolAddress((void**)&sh,    g_sh);
    cudaGetSymbolAddress((void**)&e1,    g_e1);
    cudaGetSymbolAddress((void**)&e2,    g_e2);
    cudaGetSymbolAddress((void**)&eo,    g_eo);
    cudaGetSymbolAddress((void**)&rprob, g_rprob);
    cudaGetSymbolAddress((void**)&topv,  g_topv);
    cudaGetSymbolAddress((void**)&topi,  g_topi);
    cudaGetSymbolAddress((void**)&posArr,g_pos);
    cudaGetSymbolAddress((void**)&cnt,   g_cnt);
    cudaGetSymbolAddress((void**)&idx,   g_idx);
    cudaGetSymbolAddress((void**)&psum,  g_psum);
    cudaGetSymbolAddress((void**)&sgate, g_sgate);

    // streams/events/attributes set up once, outside graph capture
    static cudaStream_t s1 = nullptr, s2 = nullptr;
    static cudaEvent_t ev[8];
    if (!s1) {
        cudaStreamCreateWithFlags(&s1, cudaStreamNonBlocking);
        cudaStreamCreateWithFlags(&s2, cudaStreamNonBlocking);
        for (int i = 0; i < 8; i++)
            cudaEventCreateWithFlags(&ev[i], cudaEventDisableTiming);
        cudaFuncSetAttribute(gemm_tc, cudaFuncAttributeMaxDynamicSharedMemorySize,
                             GSMEM);
    }
    cudaStream_t s0 = 0;

    dim3 gFull(HID / BN, TKN / BM, 1);
    dim3 gKV((NKV * HD) / BN, TKN / BM, 1);
    dim3 gII(II / BN, TKN / BM, 1);
    dim3 gExp(II / BN, TKN / BM, NEXP);

    zerocnt_k<<<1, 32, 0, s0>>>(cnt);

    // attention branch
    rmsnorm_k<<<TKN, 256, 0, s0>>>(hidden, ln1, xn1);
    cudaEventRecord(ev[0], s0);
    cudaStreamWaitEvent(s1, ev[0], 0);
    cudaStreamWaitEvent(s2, ev[0], 0);
    gemm_tc<<<gKV, 256, GSMEM, s1>>>(xn1, nullptr, wk, k, TKN, NKV * HD, HID,
                                     nullptr, nullptr, nullptr, 0, 0, 0);
    gemm_tc<<<gKV, 256, GSMEM, s2>>>(xn1, nullptr, wv, v, TKN, NKV * HD, HID,
                                     nullptr, nullptr, nullptr, 0, 0, 0);
    gemm_tc<<<gFull, 256, GSMEM, s0>>>(xn1, nullptr, wq, q, TKN, NH * HD, HID,
                                       nullptr, nullptr, nullptr, 0, 0, 0);
    cudaEventRecord(ev[1], s1);
    cudaStreamWaitEvent(s0, ev[1], 0);          // join k
    rope_k<<<TKN, 256, 0, s0>>>(q, k, pos);
    cudaEventRecord(ev[2], s2);
    cudaStreamWaitEvent(s0, ev[2], 0);          // join v
    dim3 gAttn(SS / TQ, NH, BB);
    attn2_k<<<gAttn, 256, 0, s0>>>(q, k, v, ctx);
    gemm_tc<<<gFull, 256, GSMEM, s0>>>(ctx, nullptr, wo, resid, TKN, HID, NH * HD,
                                       nullptr, nullptr, hidden, 0, 0, 0);

    // MoE branch
    rmsnorm_k<<<TKN, 256, 0, s0>>>(resid, ln2, x2);

    // fork shared-expert chain onto s1/s2
    cudaEventRecord(ev[3], s0);
    cudaStreamWaitEvent(s1, ev[3], 0);
    cudaStreamWaitEvent(s2, ev[3], 0);
    gemm_tc<<<gII, 256, GSMEM, s1>>>(x2, nullptr, sgw, gb, TKN, II, HID,
                                     nullptr, nullptr, nullptr, 0, 0, 0);
    gemm_tc<<<gII, 256, GSMEM, s2>>>(x2, nullptr, suw, ub, TKN, II, HID,
                                     nullptr, nullptr, nullptr, 0, 0, 0);
    sgate_k<<<TKN, 32, 0, s2>>>(x2, segw, sgate);
    cudaEventRecord(ev[4], s2);
    cudaStreamWaitEvent(s1, ev[4], 0);
    gemm_tc<<<gFull, 256, GSMEM, s1>>>(gb, ub, sdw, sh, TKN, HID, II,
                                       nullptr, nullptr, nullptr, 0, 0, 0);

    // routed chain on s0
    router_k<<<TKN, 32, 0, s0>>>(x2, rw, rprob, topi, topv);
    psum_k<<<NEXP, 256, 0, s0>>>(rprob, psum);
    scatter_k<<<(TKN + 255) / 256, 256, 0, s0>>>(topi, cnt, idx, posArr);
    gemm_tc<<<gExp, 256, GSMEM, s0>>>(x2, nullptr, egw, e1, TKN, II, HID, idx, cnt,
                                      nullptr, 0, (size_t)HID * II, (size_t)TKN * II);
    gemm_tc<<<gExp, 256, GSMEM, s0>>>(x2, nullptr, euw, e2, TKN, II, HID, idx, cnt,
                                      nullptr, 0, (size_t)HID * II, (size_t)TKN * II);
    gemm_tc<<<gExp, 256, GSMEM, s0>>>(e1, e2, edw, eo, TKN, HID, II, nullptr, cnt,
                                      nullptr, (size_t)TKN * II, (size_t)II * HID,
                                      (size_t)TKN * HID);

    // join shared chain
    cudaEventRecord(ev[5], s1);
    cudaStreamWaitEvent(s0, ev[5], 0);

    // combine
    int n = TKN * HID;
    int ncopy = out_size < n ? out_size : n;
    final_k<<<(n + 255) / 256, 256, 0, s0>>>(resid, eo, topi, topv, posArr,
                                             sh, sgate, out, ncopy);
    aux_k<<<1, 32, 0, s0>>>(psum, out, out_size > n ? 1 : 0, n);
}

// round 14
// speedup vs baseline: 19.2755x; 1.0049x over previous
#include <cuda_runtime.h>
#include <math.h>
#include <stdint.h>

// ---------------- problem constants ----------------
#define BB   2
#define SS   1024
#define TKN  2048            // BB*SS tokens
#define HID  1024
#define NH   16
#define NKV  4
#define HD   64
#define NEXP 8
#define TOPK 2
#define II   1024

// ---------------- scratch (device globals; no allocs allowed) ----------------
__device__ float g_xn1  [TKN * HID];
__device__ float g_q    [TKN * NH * HD];
__device__ float g_k    [TKN * NKV * HD];
__device__ float g_v    [TKN * NKV * HD];
__device__ float g_ctx  [TKN * HID];
__device__ float g_resid[TKN * HID];
__device__ float g_x2   [TKN * HID];
__device__ float g_gb   [TKN * II];
__device__ float g_ub   [TKN * II];
__device__ float g_sh   [TKN * HID];
__device__ float g_e1   [NEXP * TKN * II];   // expert gate
__device__ float g_e2   [NEXP * TKN * II];   // expert up
__device__ float g_eo   [NEXP * TKN * HID];  // expert down output
__device__ float g_rprob[TKN * NEXP];
__device__ float g_topv [TKN * TOPK];
__device__ int   g_topi [TKN * TOPK];
__device__ int   g_pos  [TKN * TOPK];
__device__ int   g_cnt  [NEXP];
__device__ int   g_idx  [NEXP * TKN];
__device__ float g_psum [NEXP];
__device__ float g_sgate[TKN];

// ---------------- zero counters ----------------
__global__ void zerocnt_k(int* cnt) {
    if (threadIdx.x < NEXP) cnt[threadIdx.x] = 0;
}

// ---------------- RMSNorm ----------------
__global__ __launch_bounds__(256) void rmsnorm_k(const float* __restrict__ x,
                                                 const float* __restrict__ w,
                                                 float* __restrict__ y) {
    int t = blockIdx.x;
    __shared__ float red[256];
    const float* xr = x + (size_t)t * HID;
    float s = 0.f;
    for (int i = threadIdx.x; i < HID; i += 256) { float v = xr[i]; s += v * v; }
    red[threadIdx.x] = s; __syncthreads();
    for (int st = 128; st > 0; st >>= 1) {
        if (threadIdx.x < st) red[threadIdx.x] += red[threadIdx.x + st];
        __syncthreads();
    }
    float inv = rsqrtf(red[0] / (float)HID + 1e-6f);
    float* yr = y + (size_t)t * HID;
    for (int i = threadIdx.x; i < HID; i += 256) yr[i] = w[i] * xr[i] * inv;
}

// ---------------- mma helpers ----------------
__device__ __forceinline__ void mma8(float* c, const uint32_t* a, const uint32_t* b) {
    asm volatile(
        "mma.sync.aligned.m16n8k8.row.col.f32.tf32.tf32.f32 "
        "{%0,%1,%2,%3}, {%4,%5,%6,%7}, {%8,%9}, {%0,%1,%2,%3};"
        : "+f"(c[0]), "+f"(c[1]), "+f"(c[2]), "+f"(c[3])
        : "r"(a[0]), "r"(a[1]), "r"(a[2]), "r"(a[3]), "r"(b[0]), "r"(b[1]));
}
__device__ __forceinline__ float siluf(float x) {
    return x / (1.f + __expf(-x));
}

#define CP_A16(dst, src) \
    asm volatile("cp.async.cg.shared.global [%0], [%1], 16;\n" :: "r"(dst), "l"(src))
#define CP_COMMIT() asm volatile("cp.async.commit_group;\n" ::)
#define CP_WAIT1()  asm volatile("cp.async.wait_group 1;\n" ::)

// ---------------- GEMM core (tf32 raw-bits, cp.async 3-stage, BK=32) ------
#define BM 128
#define BN 128
#define BK 32
#define STAGES 3
#define ASTR 36     // words; banks (4g + t4) mod 32 all distinct
#define BSTR 136    // words; banks (8*t4 + g) mod 32 all distinct
#define A_ELE (STAGES * BM * ASTR)
#define GSMEM ((STAGES * (BM * ASTR + BK * BSTR)) * 4)

__device__ __forceinline__ void gemm_core(
    const float* __restrict__ A, const float* __restrict__ A2,
    const float* __restrict__ B, float* __restrict__ C,
    int M, int N, int K,
    const int* __restrict__ gidx, const float* __restrict__ addend,
    int row0, int col0, float* sm)
{
    int tid = threadIdx.x, wid = tid >> 5, lane = tid & 31;
    int wm = wid >> 2, wn = wid & 3;          // warp tile 64x32
    int g = lane >> 2, t4 = lane & 3;
    uint32_t sbase = (uint32_t)__cvta_generic_to_shared(sm);

    float acc[4][4][4];
    #pragma unroll
    for (int i = 0; i < 4; i++)
        #pragma unroll
        for (int j = 0; j < 4; j++)
            #pragma unroll
            for (int l = 0; l < 4; l++) acc[i][j][l] = 0.f;

    int aRow[4], aCol[4], bRow[4], bCol[4];
    #pragma unroll
    for (int l = 0; l < 4; l++) {
        int f = tid + l * 256;
        aRow[l] = f >> 3;  aCol[l] = (f & 7) * 4;    // 8 float4 per 32-wide row
        bRow[l] = f >> 5;  bCol[l] = (f & 31) * 4;   // 32 float4 per 128-wide row
    }

    int nCh = K / BK;

    auto issue = [&](int kc) {
        if (kc < nCh) {
            int k0 = kc * BK, st = kc % STAGES;
            if (!A2) {
                #pragma unroll
                for (int l = 0; l < 4; l++) {
                    int gr = row0 + aRow[l];
                    if (gr >= M) gr = M - 1;          // clamp: valid addr, row unused
                    int ar = gidx ? gidx[gr] : gr;
                    CP_A16(sbase + (uint32_t)(((st * BM + aRow[l]) * ASTR + aCol[l]) * 4),
                           A + (size_t)ar * K + k0 + aCol[l]);
                }
            } else {
                #pragma unroll
                for (int l = 0; l < 4; l++) {
                    int gr = row0 + aRow[l];
                    int ar = (gr < M) ? gr : (M - 1);
                    size_t off = (size_t)ar * K + k0 + aCol[l];
                    float4 a = *(const float4*)&A[off];
                    float4 u = *(const float4*)&A2[off];
                    a.x = siluf(a.x) * u.x; a.y = siluf(a.y) * u.y;
                    a.z = siluf(a.z) * u.z; a.w = siluf(a.w) * u.w;
                    *(float4*)&sm[(st * BM + aRow[l]) * ASTR + aCol[l]] = a;
                }
            }
            #pragma unroll
            for (int l = 0; l < 4; l++) {
                CP_A16(sbase + (uint32_t)((A_ELE + (st * BK + bRow[l]) * BSTR + bCol[l]) * 4),
                       B + (size_t)(k0 + bRow[l]) * N + col0 + bCol[l]);
            }
        }
        CP_COMMIT();
    };

    issue(0);
    issue(1);

    for (int kc = 0; kc < nCh; kc++) {
        CP_WAIT1();
        __syncthreads();
        issue(kc + 2);
        int cur = kc % STAGES;
        const float* Ab = sm + cur * BM * ASTR;
        const float* Bb = sm + A_ELE + cur * BK * BSTR;
        #pragma unroll
        for (int ks = 0; ks < 4; ks++) {
            int kb = ks * 8;
            uint32_t bf[4][2];
            #pragma unroll
            for (int nt = 0; nt < 4; nt++)
                #pragma unroll
                for (int i = 0; i < 2; i++)
                    bf[nt][i] = __float_as_uint(
                        Bb[(kb + t4 + i * 4) * BSTR + wn * 32 + nt * 8 + g]);
            #pragma unroll
            for (int mt = 0; mt < 4; mt++) {
                uint32_t af[4];
                #pragma unroll
                for (int i = 0; i < 4; i++)
                    af[i] = __float_as_uint(
                        Ab[(wm * 64 + mt * 16 + g + ((i & 1) ? 8 : 0)) * ASTR
                           + kb + t4 + ((i & 2) ? 4 : 0)]);
                #pragma unroll
                for (int nt = 0; nt < 4; nt++)
                    mma8(acc[mt][nt], af, bf[nt]);
            }
        }
    }

    #pragma unroll
    for (int mt = 0; mt < 4; mt++) {
        #pragma unroll
        for (int half = 0; half < 2; half++) {
            int r = row0 + wm * 64 + mt * 16 + g + half * 8;
            if (r >= M) continue;
            #pragma unroll
            for (int nt = 0; nt < 4; nt++) {
                int c = col0 + wn * 32 + nt * 8 + t4 * 2;
                size_t o = (size_t)r * N + c;
                float2 v;
                v.x = acc[mt][nt][half * 2 + 0];
                v.y = acc[mt][nt][half * 2 + 1];
                if (addend) {
                    float2 ad = *(const float2*)&addend[o];
                    v.x += ad.x; v.y += ad.y;
                }
                *(float2*)&C[o] = v;
            }
        }
    }
}

// generic wrapper (per-z strides, gather, dynamic M, addend, fused silu)
__global__ __launch_bounds__(256, 2) void gemm_tc(
    const float* __restrict__ A, const float* __restrict__ A2,
    const float* __restrict__ B,
    float* __restrict__ C, int Mfixed, int N, int K,
    const int* __restrict__ gidx, const int* __restrict__ cntPtr,
    const float* __restrict__ addend,
    size_t Az, size_t Bz, size_t Cz)
{
    extern __shared__ float sm[];
    int ez = blockIdx.z;
    int M = cntPtr ? cntPtr[ez] : Mfixed;
    int row0 = blockIdx.y * BM;
    if (row0 >= M) return;
    A += (size_t)ez * Az; B += (size_t)ez * Bz; C += (size_t)ez * Cz;
    if (A2) A2 += (size_t)ez * Az;
    const int* gi = gidx ? gidx + (size_t)ez * TKN : nullptr;
    gemm_core(A, A2, B, C, M, N, K, gi, addend, row0, blockIdx.x * BN, sm);
}

// fused QKV: grid.x sections 0-7 -> wq, 8-9 -> wk, 10-11 -> wv
__global__ __launch_bounds__(256, 2) void gemm_qkv(
    const float* __restrict__ X,
    const float* __restrict__ wq, const float* __restrict__ wk,
    const float* __restrict__ wv,
    float* __restrict__ q, float* __restrict__ k, float* __restrict__ v)
{
    extern __shared__ float sm[];
    int x = blockIdx.x;
    const float* B; float* C; int N, col0;
    if (x < 8)       { B = wq; C = q; N = NH * HD;  col0 = x * BN; }
    else if (x < 10) { B = wk; C = k; N = NKV * HD; col0 = (x - 8) * BN; }
    else             { B = wv; C = v; N = NKV * HD; col0 = (x - 10) * BN; }
    gemm_core(X, nullptr, B, C, TKN, N, HID, nullptr, nullptr,
              blockIdx.y * BM, col0, sm);
}

// dual GEMM: same A, two outputs (grid.x split in half)
__global__ __launch_bounds__(256, 2) void gemm_dual(
    const float* __restrict__ A,
    const float* __restrict__ B1, float* __restrict__ C1,
    const float* __restrict__ B2, float* __restrict__ C2,
    int Mfixed, int N, int K,
    const int* __restrict__ gidx, const int* __restrict__ cntPtr,
    size_t Bz, size_t Cz)
{
    extern __shared__ float sm[];
    int ez = blockIdx.z;
    int M = cntPtr ? cntPtr[ez] : Mfixed;
    int row0 = blockIdx.y * BM;
    if (row0 >= M) return;
    int half = gridDim.x >> 1;
    int x = blockIdx.x;
    const float* B = (x < half) ? B1 : B2;
    float* C = (x < half) ? C1 : C2;
    int col0 = ((x < half) ? x : x - half) * BN;
    B += (size_t)ez * Bz; C += (size_t)ez * Cz;
    const int* gi = gidx ? gidx + (size_t)ez * TKN : nullptr;
    gemm_core(A, nullptr, B, C, M, N, K, gi, nullptr, row0, col0, sm);
}

// ---------------- RoPE (in-place on q,k) ----------------
__global__ __launch_bounds__(256) void rope_k(float* __restrict__ Q,
                                              float* __restrict__ Kb,
                                              const int* __restrict__ pos_ids) {
    int t = blockIdx.x;
    float pos = (float)pos_ids[t];
    int tid = threadIdx.x;
    for (int p = tid; p < NH * 32; p += 256) {
        int hh = p >> 5, d = p & 31;
        float invf = powf(1.0e6f, -(float)d / 32.f);
        float s, c; sincosf(pos * invf, &s, &c);
        size_t base = (size_t)t * (NH * HD) + hh * HD;
        float x1 = Q[base + d], x2 = Q[base + d + 32];
        Q[base + d]      = x1 * c - x2 * s;
        Q[base + d + 32] = x2 * c + x1 * s;
    }
    if (tid < NKV * 32) {
        int hh = tid >> 5, d = tid & 31;
        float invf = powf(1.0e6f, -(float)d / 32.f);
        float s, c; sincosf(pos * invf, &s, &c);
        size_t base = (size_t)t * (NKV * HD) + hh * HD;
        float x1 = Kb[base + d], x2 = Kb[base + d + 32];
        Kb[base + d]      = x1 * c - x2 * s;
        Kb[base + d + 32] = x2 * c + x1 * s;
    }
}

// ---------------- tiled causal attention with online softmax --------------
#define TQ  64
#define CKC 32

__global__ __launch_bounds__(256) void attn2_k(const float* __restrict__ Q,
                                               const float* __restrict__ Kb,
                                               const float* __restrict__ Vb,
                                               float* __restrict__ ctx) {
    int qtile = gridDim.x - 1 - blockIdx.x;
    int h = blockIdx.y, b = blockIdx.z;
    int kv = h >> 2;
    __shared__ float Qs[TQ][HD];
    __shared__ float Ks[CKC][68];
    __shared__ float Vs[CKC][HD];
    __shared__ float Ps[TQ][CKC];
    int tid = threadIdx.x, wid = tid >> 5, lane = tid & 31;

    for (int i = tid; i < TQ * HD / 4; i += 256) {
        int r = i >> 4, c4 = i & 15;
        int t = b * SS + qtile * TQ + r;
        ((float4*)Qs[r])[c4] =
            *(const float4*)&Q[(size_t)t * (NH * HD) + h * HD + c4 * 4];
    }

    float m[8], l[8], o0[8], o1[8];
    #pragma unroll
    for (int r = 0; r < 8; r++) { m[r] = -1e30f; l[r] = 0.f; o0[r] = 0.f; o1[r] = 0.f; }
    int row0 = wid * 8;
    int d0 = lane * 2;
    int nch = (qtile + 1) * (TQ / CKC);

    for (int kc = 0; kc < nch; kc++) {
        __syncthreads();
        for (int i = tid; i < CKC * HD / 4; i += 256) {
            int r = i >> 4, c4 = i & 15;
            int t = b * SS + kc * CKC + r;
            size_t base = (size_t)t * (NKV * HD) + kv * HD + c4 * 4;
            *(float4*)&Ks[r][c4 * 4] = *(const float4*)&Kb[base];
            *(float4*)&Vs[r][c4 * 4] = *(const float4*)&Vb[base];
        }
        __syncthreads();
        float s[8];
        #pragma unroll
        for (int r = 0; r < 8; r++) s[r] = 0.f;
        #pragma unroll 4
        for (int d4 = 0; d4 < 16; d4++) {
            float4 k4 = *(const float4*)&Ks[lane][d4 * 4];
            #pragma unroll
            for (int r = 0; r < 8; r++) {
                float4 q4 = ((const float4*)Qs[row0 + r])[d4];
                s[r] += q4.x * k4.x + q4.y * k4.y + q4.z * k4.z + q4.w * k4.w;
            }
        }
        int kpos = kc * CKC + lane;
        #pragma unroll
        for (int r = 0; r < 8; r++) {
            float sv = s[r] * 0.125f;
            int qpos = qtile * TQ + row0 + r;
            if (kpos > qpos) sv = -1e30f;
            float cm = sv;
            #pragma unroll
            for (int off = 16; off; off >>= 1)
                cm = fmaxf(cm, __shfl_xor_sync(0xffffffffu, cm, off));
            float mnew = fmaxf(m[r], cm);
            float p = __expf(sv - mnew);
            float rs = p;
            #pragma unroll
            for (int off = 16; off; off >>= 1)
                rs += __shfl_xor_sync(0xffffffffu, rs, off);
            float alpha = __expf(m[r] - mnew);
            l[r] = l[r] * alpha + rs;
            o0[r] *= alpha; o1[r] *= alpha;
            m[r] = mnew;
            Ps[row0 + r][lane] = p;
        }
        __syncwarp();
        #pragma unroll 4
        for (int kp = 0; kp < CKC / 2; kp++) {
            float2 va = *(const float2*)&Vs[kp * 2][d0];
            float2 vb = *(const float2*)&Vs[kp * 2 + 1][d0];
            #pragma unroll
            for (int r = 0; r < 8; r++) {
                float2 p2 = ((const float2*)Ps[row0 + r])[kp];
                o0[r] += p2.x * va.x + p2.y * vb.x;
                o1[r] += p2.x * va.y + p2.y * vb.y;
            }
        }
    }
    #pragma unroll
    for (int r = 0; r < 8; r++) {
        int t = b * SS + qtile * TQ + row0 + r;
        float inv = 1.f / l[r];
        float2 res = make_float2(o0[r] * inv, o1[r] * inv);
        *(float2*)&ctx[(size_t)t * (NH * HD) + h * HD + d0] = res;
    }
}

// ---------------- router ----------------
__global__ __launch_bounds__(32) void router_k(const float* __restrict__ x2,
                                               const float* __restrict__ rw,
                                               float* __restrict__ rprob,
                                               int* __restrict__ topi,
                                               float* __restrict__ topv) {
    int t = blockIdx.x, lane = threadIdx.x;
    float part[NEXP] = {};
    const float* xr = x2 + (size_t)t * HID;
    for (int k = lane; k < HID; k += 32) {
        float xv = xr[k];
        #pragma unroll
        for (int e = 0; e < NEXP; e++) part[e] += xv * rw[k * NEXP + e];
    }
    #pragma unroll
    for (int e = 0; e < NEXP; e++)
        for (int off = 16; off; off >>= 1)
            part[e] += __shfl_xor_sync(0xffffffff, part[e], off);
    if (lane == 0) {
        float m = part[0];
        #pragma unroll
        for (int e = 1; e < NEXP; e++) m = fmaxf(m, part[e]);
        float p[NEXP], s = 0.f;
        #pragma unroll
        for (int e = 0; e < NEXP; e++) { p[e] = expf(part[e] - m); s += p[e]; }
        #pragma unroll
        for (int e = 0; e < NEXP; e++) { p[e] /= s; rprob[t * NEXP + e] = p[e]; }
        int i1 = 0; float v1 = p[0];
        for (int e = 1; e < NEXP; e++) if (p[e] > v1) { v1 = p[e]; i1 = e; }
        int i2 = -1; float v2 = -1.f;
        for (int e = 0; e < NEXP; e++) if (e != i1 && p[e] > v2) { v2 = p[e]; i2 = e; }
        topi[t * 2]     = i1; topv[t * 2]     = v1;
        topi[t * 2 + 1] = i2; topv[t * 2 + 1] = v2;
    }
}

// deterministic per-expert prob sum (for aux)
__global__ __launch_bounds__(256) void psum_k(const float* __restrict__ rprob,
                                              float* __restrict__ psum) {
    int e = blockIdx.x;
    __shared__ float red[256];
    float s = 0.f;
    for (int t = threadIdx.x; t < TKN; t += 256) s += rprob[t * NEXP + e];
    red[threadIdx.x] = s; __syncthreads();
    for (int st = 128; st > 0; st >>= 1) {
        if (threadIdx.x < st) red[threadIdx.x] += red[threadIdx.x + st];
        __syncthreads();
    }
    if (threadIdx.x == 0) psum[e] = red[0];
}

// build per-expert token lists (records position for later gather)
__global__ void scatter_k(const int* __restrict__ topi,
                          int* cnt, int* idx, int* posArr) {
    int t = blockIdx.x * 256 + threadIdx.x;
    if (t >= TKN) return;
    for (int j = 0; j < TOPK; j++) {
        int e = topi[t * 2 + j];
        int pos = atomicAdd(&cnt[e], 1);
        idx[e * TKN + pos] = t;
        posArr[t * 2 + j] = pos;
    }
}

// shared-expert sigmoid gate
__global__ __launch_bounds__(32) void sgate_k(const float* __restrict__ x2,
                                              const float* __restrict__ seg,
                                              float* __restrict__ sgate) {
    int t = blockIdx.x, lane = threadIdx.x;
    const float* xr = x2 + (size_t)t * HID;
    float s = 0.f;
    for (int k = lane; k < HID; k += 32) s += xr[k] * seg[k];
    for (int off = 16; off; off >>= 1) s += __shfl_xor_sync(0xffffffff, s, off);
    if (lane == 0) sgate[t] = 1.f / (1.f + expf(-s));
}

// out = resid + sum_j topv*expert_down[j] + sgate * shared
__global__ void final_k(const float* __restrict__ resid,
                        const float* __restrict__ yb,
                        const int* __restrict__ topi, const float* __restrict__ topv,
                        const int* __restrict__ posArr,
                        const float* __restrict__ sh, const float* __restrict__ sgate,
                        float* __restrict__ out, int n) {
    int i = blockIdx.x * 256 + threadIdx.x;
    if (i >= n) return;
    int t = i >> 10;
    int col = i & 1023;
    float moe = 0.f;
    #pragma unroll
    for (int j = 0; j < TOPK; j++) {
        int e = topi[t * 2 + j];
        int p = posArr[t * 2 + j];
        moe += topv[t * 2 + j] * yb[((size_t)e * TKN + p) * HID + col];
    }
    out[i] = resid[i] + moe + sgate[t] * sh[i];
}

__global__ void aux_k(const float* __restrict__ psum, float* __restrict__ out,
                      int doWrite, int pos) {
    if (threadIdx.x == 0 && doWrite) {
        float a = 0.f;
        for (int e = 0; e < NEXP; e++) {
            float d = psum[e] / (float)TKN - 1.f / (float)NEXP;
            a += d * d;
        }
        out[pos] = a / (float)NEXP;
    }
}

// ---------------- launch ----------------
extern "C" void kernel_launch(void* const* d_in, const int* in_sizes, int n_in,
                              void* d_out, int out_size) {
    const float* hidden = (const float*)d_in[0];
    const int*   pos  = (const int*)  d_in[2];
    const float* ln1  = (const float*)d_in[3];
    const float* ln2  = (const float*)d_in[4];
    const float* wq   = (const float*)d_in[5];
    const float* wk   = (const float*)d_in[6];
    const float* wv   = (const float*)d_in[7];
    const float* wo   = (const float*)d_in[8];
    const float* rw   = (const float*)d_in[9];
    const float* egw  = (const float*)d_in[10];
    const float* euw  = (const float*)d_in[11];
    const float* edw  = (const float*)d_in[12];
    const float* sgw  = (const float*)d_in[13];
    const float* suw  = (const float*)d_in[14];
    const float* sdw  = (const float*)d_in[15];
    const float* segw = (const float*)d_in[16];
    float* out = (float*)d_out;

    float *xn1, *q, *k, *v, *ctx, *resid, *x2, *gb, *ub, *sh, *e1, *e2, *eo;
    float *rprob, *topv, *psum, *sgate;
    int *topi, *cnt, *idx, *posArr;
    cudaGetSymbolAddress((void**)&xn1,   g_xn1);
    cudaGetSymbolAddress((void**)&q,     g_q);
    cudaGetSymbolAddress((void**)&k,     g_k);
    cudaGetSymbolAddress((void**)&v,     g_v);
    cudaGetSymbolAddress((void**)&ctx,   g_ctx);
    cudaGetSymbolAddress((void**)&resid, g_resid);
    cudaGetSymbolAddress((void**)&x2,    g_x2);
    cudaGetSymbolAddress((void**)&gb,    g_gb);
    cudaGetSymbolAddress((void**)&ub,    g_ub);
    cudaGetSymbolAddress((void**)&sh,    g_sh);
    cudaGetSymbolAddress((void**)&e1,    g_e1);
    cudaGetSymbolAddress((void**)&e2,    g_e2);
    cudaGetSymbolAddress((void**)&eo,    g_eo);
    cudaGetSymbolAddress((void**)&rprob, g_rprob);
    cudaGetSymbolAddress((void**)&topv,  g_topv);
    cudaGetSymbolAddress((void**)&topi,  g_topi);
    cudaGetSymbolAddress((void**)&posArr,g_pos);
    cudaGetSymbolAddress((void**)&cnt,   g_cnt);
    cudaGetSymbolAddress((void**)&idx,   g_idx);
    cudaGetSymbolAddress((void**)&psum,  g_psum);
    cudaGetSymbolAddress((void**)&sgate, g_sgate);

    // streams/events/attributes set up once, outside graph capture
    static cudaStream_t s1 = nullptr, s2 = nullptr;
    static cudaEvent_t ev[8];
    if (!s1) {
        cudaStreamCreateWithFlags(&s1, cudaStreamNonBlocking);
        cudaStreamCreateWithFlags(&s2, cudaStreamNonBlocking);
        for (int i = 0; i < 8; i++)
            cudaEventCreateWithFlags(&ev[i], cudaEventDisableTiming);
        cudaFuncSetAttribute(gemm_tc,  cudaFuncAttributeMaxDynamicSharedMemorySize, GSMEM);
        cudaFuncSetAttribute(gemm_qkv, cudaFuncAttributeMaxDynamicSharedMemorySize, GSMEM);
        cudaFuncSetAttribute(gemm_dual,cudaFuncAttributeMaxDynamicSharedMemorySize, GSMEM);
    }
    cudaStream_t s0 = 0;

    dim3 gFull(HID / BN, TKN / BM, 1);          // 8 x 16
    dim3 gQKV(12, TKN / BM, 1);                 // 12 x 16 (8 q + 2 k + 2 v)
    dim3 gDualSh(2 * II / BN, TKN / BM, 1);     // 16 x 16
    dim3 gDualEx(2 * II / BN, TKN / BM, NEXP);  // 16 x 16 x 8
    dim3 gExpDown(HID / BN, TKN / BM, NEXP);    // 8 x 16 x 8

    zerocnt_k<<<1, 32, 0, s0>>>(cnt);

    // attention branch
    rmsnorm_k<<<TKN, 256, 0, s0>>>(hidden, ln1, xn1);
    gemm_qkv<<<gQKV, 256, GSMEM, s0>>>(xn1, wq, wk, wv, q, k, v);
    rope_k<<<TKN, 256, 0, s0>>>(q, k, pos);
    dim3 gAttn(SS / TQ, NH, BB);
    attn2_k<<<gAttn, 256, 0, s0>>>(q, k, v, ctx);
    gemm_tc<<<gFull, 256, GSMEM, s0>>>(ctx, nullptr, wo, resid, TKN, HID, NH * HD,
                                       nullptr, nullptr, hidden, 0, 0, 0);

    // MoE branch
    rmsnorm_k<<<TKN, 256, 0, s0>>>(resid, ln2, x2);

    // fork shared-expert chain onto s1, sgate onto s2
    cudaEventRecord(ev[3], s0);
    cudaStreamWaitEvent(s1, ev[3], 0);
    cudaStreamWaitEvent(s2, ev[3], 0);
    gemm_dual<<<gDualSh, 256, GSMEM, s1>>>(x2, sgw, gb, suw, ub, TKN, II, HID,
                                           nullptr, nullptr, 0, 0);
    gemm_tc<<<gFull, 256, GSMEM, s1>>>(gb, ub, sdw, sh, TKN, HID, II,
                                       nullptr, nullptr, nullptr, 0, 0, 0);
    sgate_k<<<TKN, 32, 0, s2>>>(x2, segw, sgate);

    // routed chain on s0
    router_k<<<TKN, 32, 0, s0>>>(x2, rw, rprob, topi, topv);
    psum_k<<<NEXP, 256, 0, s0>>>(rprob, psum);
    scatter_k<<<(TKN + 255) / 256, 256, 0, s0>>>(topi, cnt, idx, posArr);
    gemm_dual<<<gDualEx, 256, GSMEM, s0>>>(x2, egw, e1, euw, e2, TKN, II, HID,
                                           idx, cnt, (size_t)HID * II,
                                           (size_t)TKN * II);
    gemm_tc<<<gExpDown, 256, GSMEM, s0>>>(e1, e2, edw, eo, TKN, HID, II,
                                          nullptr, cnt, nullptr,
                                          (size_t)TKN * II, (size_t)II * HID,
                                          (size_t)TKN * HID);

    // join shared chain + sgate
    cudaEventRecord(ev[5], s1);
    cudaStreamWaitEvent(s0, ev[5], 0);
    cudaEventRecord(ev[6], s2);
    cudaStreamWaitEvent(s0, ev[6], 0);

    // combine
    int n = TKN * HID;
    int ncopy = out_size < n ? out_size : n;
    final_k<<<(n + 255) / 256, 256, 0, s0>>>(resid, eo, topi, topv, posArr,
                                             sh, sgate, out, ncopy);
    aux_k<<<1, 32, 0, s0>>>(psum, out, out_size > n ? 1 : 0, n);
}